// round 6
// baseline (speedup 1.0000x reference)
#include <cuda_runtime.h>
#include <math.h>
#include <stdint.h>

#define NTOK 8192
#define DDIM 1024
#define APW  249            // band: |i-j| <= 249
#define BANDW 512           // raw logits band stride
#define NSLAB (NTOK / 128)  // 64 j-blocks
#define SLABR 640           // slab rows: i in [jb*128-256, jb*128+384)

// ---------------- scratch (static device arrays; zero-initialized) ----------------
__device__ float g_xh [(size_t)NTOK * DDIM];
__device__ float g_xl [(size_t)NTOK * DDIM];
__device__ float g_Wq [DDIM * DDIM];
__device__ float g_Wk [DDIM * DDIM];
__device__ float g_Wv [DDIM * DDIM];
__device__ float g_Wo [DDIM * DDIM];
__device__ float g_Qh [(size_t)NTOK * DDIM];
__device__ float g_Ql [(size_t)NTOK * DDIM];
__device__ float g_Kh [(size_t)NTOK * DDIM];
__device__ float g_Kl [(size_t)NTOK * DDIM];
__device__ float g_V  [(size_t)NTOK * DDIM];               // tf32-rounded
__device__ float g_S  [(size_t)NTOK * BANDW];              // raw logits band
__device__ float g_AH [(size_t)NSLAB * SLABR * 128];       // att hi slabs
__device__ float g_AL [(size_t)NSLAB * SLABR * 128];       // att lo slabs
__device__ float g_y0h[(size_t)NTOK * DDIM];
__device__ float g_y0l[(size_t)NTOK * DDIM];

// ---------------- helpers ----------------
__device__ __forceinline__ uint32_t f2tf32(float f) {
    uint32_t u;
    asm("cvt.rna.tf32.f32 %0, %1;" : "=r"(u) : "f"(f));
    return u;
}
__device__ __forceinline__ float tf32f(float f) { return __uint_as_float(f2tf32(f)); }

__device__ __forceinline__ void mma_tf32(float c[4], const float a[4], const float b[2]) {
    asm volatile(
        "mma.sync.aligned.m16n8k8.row.col.f32.tf32.tf32.f32 "
        "{%0,%1,%2,%3}, {%4,%5,%6,%7}, {%8,%9}, {%0,%1,%2,%3};"
        : "+f"(c[0]), "+f"(c[1]), "+f"(c[2]), "+f"(c[3])
        : "r"(__float_as_uint(a[0])), "r"(__float_as_uint(a[1])),
          "r"(__float_as_uint(a[2])), "r"(__float_as_uint(a[3])),
          "r"(__float_as_uint(b[0])), "r"(__float_as_uint(b[1])));
}

__device__ __forceinline__ uint32_t s2u(const void* p) {
    return (uint32_t)__cvta_generic_to_shared(p);
}
__device__ __forceinline__ void cpa16(uint32_t dst, const float* src) {
    asm volatile("cp.async.cg.shared.global [%0], [%1], 16;" :: "r"(dst), "l"(src));
}
__device__ __forceinline__ void cpa16p(uint32_t dst, const float* src, bool ok) {
    int sz = ok ? 16 : 0;
    asm volatile("cp.async.cg.shared.global [%0], [%1], 16, %2;" :: "r"(dst), "l"(src), "r"(sz));
}
#define CPA_COMMIT() asm volatile("cp.async.commit_group;")
#define CPA_WAIT1()  asm volatile("cp.async.wait_group 1;")

// ---------------- prep: split / round ----------------
__global__ void split_k(const float* __restrict__ src, float* __restrict__ hi,
                        float* __restrict__ lo, int n) {
    int i = blockIdx.x * blockDim.x + threadIdx.x;
    if (i < n) {
        float v = src[i];
        float h = tf32f(v);
        hi[i] = h;
        lo[i] = tf32f(v - h);
    }
}
__global__ void round_k(const float* __restrict__ src, float* __restrict__ dst, int n) {
    int i = blockIdx.x * blockDim.x + threadIdx.x;
    if (i < n) dst[i] = tf32f(src[i]);
}

// =====================================================================
// Engine: C = alpha * (Ah [+Al]) @ B^T, row-major, tf32 tensor cores.
// 128x128x32 block, 128 threads = 4 warps, warp tile 64x64.
// XOR-swizzled smem (16B chunks ^ (row&7)): conflict-free, no padding.
// OUT: 0 = fp32, 1 = tf32-rounded, 2 = split (C=hi, C2=lo)
// =====================================================================
#define MTS 4096            // 128 rows * 32 floats per matrix per stage

template<int AL, int OUT>
__global__ __launch_bounds__(128) void gemm2(
    const float* __restrict__ Ah, const float* __restrict__ Al,
    const float* __restrict__ B,
    float* __restrict__ C, float* __restrict__ C2,
    int M, int N, int K, float alpha)
{
    extern __shared__ float sm[];
    const int NMAT = AL ? 3 : 2;
    const int SST = NMAT * MTS;                 // floats per stage
    float* sAh = sm;
    float* sAl = sm + MTS;
    float* sB  = sm + (AL ? 2 : 1) * MTS;

    const int t = threadIdx.x;
    const int warp = t >> 5, lane = t & 31;
    const int g = lane >> 2, tig = lane & 3;
    const int wm = warp >> 1, wn = warp & 1;

    const int rowA0 = blockIdx.y * 128;
    const int rowB0 = blockIdx.x * 128;

    const float* gA  = Ah + (size_t)(rowA0 + t) * K;
    const float* gA2 = AL ? (Al + (size_t)(rowA0 + t) * K) : gA;
    const float* gB  = B  + (size_t)(rowB0 + t) * K;

    const uint32_t bAh = s2u(sAh) + t * 128;    // bytes (32 floats/row)
    const uint32_t bAl = s2u(sAl) + t * 128;
    const uint32_t bB  = s2u(sB)  + t * 128;
    const int r7 = t & 7;

    float acc[4][8][4] = {};

    auto issue = [&](int kt, int s) {
        const int k0 = kt * 32;
        const uint32_t so = (uint32_t)s * SST * 4;
        #pragma unroll
        for (int j = 0; j < 8; j++) {
            const uint32_t d = (uint32_t)((j ^ r7) * 16);
            cpa16(bAh + so + d, gA + k0 + j * 4);
            if (AL) cpa16(bAl + so + d, gA2 + k0 + j * 4);
            cpa16(bB + so + d, gB + k0 + j * 4);
        }
    };

    const int KT = K / 32;
    issue(0, 0);
    CPA_COMMIT();

    for (int kt = 0; kt < KT; kt++) {
        const int s = kt & 1;
        if (kt + 1 < KT) issue(kt + 1, s ^ 1);
        CPA_COMMIT();
        CPA_WAIT1();
        __syncthreads();

        const float* pA  = sAh + s * SST;
        const float* pA2 = sAl + s * SST;
        const float* pB  = sB  + s * SST;

        #pragma unroll
        for (int k8 = 0; k8 < 4; k8++) {
            const int c0 = (2 * k8) ^ g;        // swizzled chunk for kk
            const int c1 = c0 ^ 1;              // for kk+4
            const int o0 = c0 * 4 + tig;
            const int o1 = c1 * 4 + tig;
            float a[4][4], a2[4][4], b[8][2];
            #pragma unroll
            for (int fm = 0; fm < 4; fm++) {
                const int m = (wm * 64 + fm * 16 + g) * 32;
                a[fm][0] = pA[m + o0];
                a[fm][1] = pA[m + 256 + o0];    // +8 rows * 32
                a[fm][2] = pA[m + o1];
                a[fm][3] = pA[m + 256 + o1];
                if (AL) {
                    a2[fm][0] = pA2[m + o0];
                    a2[fm][1] = pA2[m + 256 + o0];
                    a2[fm][2] = pA2[m + o1];
                    a2[fm][3] = pA2[m + 256 + o1];
                }
            }
            #pragma unroll
            for (int fn = 0; fn < 8; fn++) {
                const int n = (wn * 64 + fn * 8 + g) * 32;
                b[fn][0] = pB[n + o0];
                b[fn][1] = pB[n + o1];
            }
            #pragma unroll
            for (int fm = 0; fm < 4; fm++)
                #pragma unroll
                for (int fn = 0; fn < 8; fn++) {
                    mma_tf32(acc[fm][fn], a[fm], b[fn]);
                    if (AL) mma_tf32(acc[fm][fn], a2[fm], b[fn]);
                }
        }
        __syncthreads();
    }

    #pragma unroll
    for (int fm = 0; fm < 4; fm++) {
        #pragma unroll
        for (int half = 0; half < 2; half++) {
            const int m0 = rowA0 + wm * 64 + fm * 16 + g + half * 8;
            #pragma unroll
            for (int fn = 0; fn < 8; fn++) {
                const int n0 = rowB0 + wn * 64 + fn * 8 + 2 * tig;
                const size_t base = (size_t)m0 * N + n0;
                #pragma unroll
                for (int c = 0; c < 2; c++) {
                    float v = alpha * acc[fm][fn][half * 2 + c];
                    if (OUT == 0) C[base + c] = v;
                    else if (OUT == 1) C[base + c] = tf32f(v);
                    else {
                        float h = tf32f(v);
                        C[base + c]  = h;
                        C2[base + c] = tf32f(v - h);
                    }
                }
            }
        }
    }
}

// =====================================================================
// Banded logits, 3-term on pre-split operands:
//   S[i][j-i+249] = (Qh+Ql)[i,:] . (Kh+Kl)[j,:]   (hh + hl + lh)
// 128x128 tiles; bx 0..4 covers j in [i0-249, i0+391); K rows predicated.
// =====================================================================
__global__ __launch_bounds__(128) void qk3_mma()
{
    extern __shared__ float sm[];
    const int SST = 4 * MTS;
    float* sQh = sm;
    float* sQl = sm + MTS;
    float* sKh = sm + 2 * MTS;
    float* sKl = sm + 3 * MTS;

    const int t = threadIdx.x;
    const int warp = t >> 5, lane = t & 31;
    const int g = lane >> 2, tig = lane & 3;
    const int wm = warp >> 1, wn = warp & 1;

    const int i0 = blockIdx.y * 128;
    const int j0 = i0 - APW + (int)blockIdx.x * 128;

    const int jr = j0 + t;
    const bool jok = ((unsigned)jr < (unsigned)NTOK);
    const int jrc = jok ? jr : 0;

    const float* gQh = g_Qh + (size_t)(i0 + t) * DDIM;
    const float* gQl = g_Ql + (size_t)(i0 + t) * DDIM;
    const float* gKh = g_Kh + (size_t)jrc * DDIM;
    const float* gKl = g_Kl + (size_t)jrc * DDIM;

    const uint32_t bQh = s2u(sQh) + t * 128;
    const uint32_t bQl = s2u(sQl) + t * 128;
    const uint32_t bKh = s2u(sKh) + t * 128;
    const uint32_t bKl = s2u(sKl) + t * 128;
    const int r7 = t & 7;

    float acc[4][8][4] = {};

    auto issue = [&](int kt, int s) {
        const int k0 = kt * 32;
        const uint32_t so = (uint32_t)s * SST * 4;
        #pragma unroll
        for (int j = 0; j < 8; j++) {
            const uint32_t d = (uint32_t)((j ^ r7) * 16);
            cpa16 (bQh + so + d, gQh + k0 + j * 4);
            cpa16 (bQl + so + d, gQl + k0 + j * 4);
            cpa16p(bKh + so + d, gKh + k0 + j * 4, jok);
            cpa16p(bKl + so + d, gKl + k0 + j * 4, jok);
        }
    };

    const int KT = DDIM / 32;
    issue(0, 0);
    CPA_COMMIT();

    for (int kt = 0; kt < KT; kt++) {
        const int s = kt & 1;
        if (kt + 1 < KT) issue(kt + 1, s ^ 1);
        CPA_COMMIT();
        CPA_WAIT1();
        __syncthreads();

        const float* pQh = sQh + s * SST;
        const float* pQl = sQl + s * SST;
        const float* pKh = sKh + s * SST;
        const float* pKl = sKl + s * SST;

        #pragma unroll
        for (int k8 = 0; k8 < 4; k8++) {
            const int c0 = (2 * k8) ^ g;
            const int c1 = c0 ^ 1;
            const int o0 = c0 * 4 + tig;
            const int o1 = c1 * 4 + tig;
            float ah[4][4], al[4][4], bh[8][2], bl[8][2];
            #pragma unroll
            for (int fm = 0; fm < 4; fm++) {
                const int m = (wm * 64 + fm * 16 + g) * 32;
                ah[fm][0] = pQh[m + o0];       ah[fm][1] = pQh[m + 256 + o0];
                ah[fm][2] = pQh[m + o1];       ah[fm][3] = pQh[m + 256 + o1];
                al[fm][0] = pQl[m + o0];       al[fm][1] = pQl[m + 256 + o0];
                al[fm][2] = pQl[m + o1];       al[fm][3] = pQl[m + 256 + o1];
            }
            #pragma unroll
            for (int fn = 0; fn < 8; fn++) {
                const int n = (wn * 64 + fn * 8 + g) * 32;
                bh[fn][0] = pKh[n + o0];       bh[fn][1] = pKh[n + o1];
                bl[fn][0] = pKl[n + o0];       bl[fn][1] = pKl[n + o1];
            }
            #pragma unroll
            for (int fm = 0; fm < 4; fm++)
                #pragma unroll
                for (int fn = 0; fn < 8; fn++) {
                    mma_tf32(acc[fm][fn], ah[fm], bh[fn]);
                    mma_tf32(acc[fm][fn], ah[fm], bl[fn]);
                    mma_tf32(acc[fm][fn], al[fm], bh[fn]);
                }
        }
        __syncthreads();
    }

    #pragma unroll
    for (int fm = 0; fm < 4; fm++) {
        #pragma unroll
        for (int half = 0; half < 2; half++) {
            const int i = i0 + wm * 64 + fm * 16 + g + half * 8;
            #pragma unroll
            for (int fn = 0; fn < 8; fn++) {
                const int jb = j0 + wn * 64 + fn * 8 + 2 * tig;
                #pragma unroll
                for (int c = 0; c < 2; c++) {
                    const int j = jb + c;
                    const int tt = j - i + APW;
                    if ((unsigned)j < (unsigned)NTOK && (unsigned)tt <= (unsigned)(2 * APW))
                        g_S[(size_t)i * BANDW + tt] = acc[fm][fn][half * 2 + c];
                }
            }
        }
    }
}

// =====================================================================
// Per-row band softmax -> d_att (fp32) + att hi/lo SLABS (aligned for attv)
// slab layout: g_AH[jb][srow][jc], jb=j>>7, srow=i-128*jb+256, jc=j&127
// =====================================================================
__global__ __launch_bounds__(256) void softmax_band_kernel(float* __restrict__ d_att,
                                                           int write_att)
{
    const int i = blockIdx.x;
    const int t = threadIdx.x;
    const int t_lo = (i < APW) ? (APW - i) : 0;
    const int jmax = (i + APW < NTOK - 1) ? (i + APW) : (NTOK - 1);
    const int t_hi = jmax - i + APW;

    const float* row = g_S + (size_t)i * BANDW;
    const int t0 = t, t1 = t + 256;
    float v0 = (t0 >= t_lo && t0 <= t_hi) ? row[t0] : -INFINITY;
    float v1 = (t1 >= t_lo && t1 <= t_hi) ? row[t1] : -INFINITY;

    __shared__ float shm[8];
    __shared__ float shs[8];
    const int lane = t & 31, warp = t >> 5;

    float m = fmaxf(v0, v1);
    #pragma unroll
    for (int o = 16; o > 0; o >>= 1) m = fmaxf(m, __shfl_xor_sync(0xffffffffu, m, o));
    if (lane == 0) shm[warp] = m;
    __syncthreads();
    if (warp == 0) {
        float mm = (lane < 8) ? shm[lane] : -INFINITY;
        #pragma unroll
        for (int o = 4; o > 0; o >>= 1) mm = fmaxf(mm, __shfl_xor_sync(0xffffffffu, mm, o));
        if (lane == 0) shm[0] = mm;
    }
    __syncthreads();
    const float M = shm[0];

    const float e0 = expf(v0 - M);
    const float e1 = expf(v1 - M);
    float s = e0 + e1;
    #pragma unroll
    for (int o = 16; o > 0; o >>= 1) s += __shfl_xor_sync(0xffffffffu, s, o);
    if (lane == 0) shs[warp] = s;
    __syncthreads();
    if (warp == 0) {
        float ss = (lane < 8) ? shs[lane] : 0.f;
        #pragma unroll
        for (int o = 4; o > 0; o >>= 1) ss += __shfl_xor_sync(0xffffffffu, ss, o);
        if (lane == 0) shs[0] = ss;
    }
    __syncthreads();
    const float inv = 1.0f / shs[0];

    #pragma unroll
    for (int q = 0; q < 2; q++) {
        const int tt = q ? t1 : t0;
        const float e = q ? e1 : e0;
        if (tt >= t_lo && tt <= t_hi) {
            const float w = e * inv;
            const int j = i - APW + tt;
            const int jb = j >> 7;
            const size_t sidx = ((size_t)jb * SLABR + (i - jb * 128 + 256)) * 128 + (j & 127);
            const float h = tf32f(w);
            g_AH[sidx] = h;
            g_AL[sidx] = tf32f(w - h);
            if (write_att) d_att[(size_t)i * NTOK + j] = w;
        }
    }
}

// =====================================================================
// attv: y0[j,d] = sum_i att[i,j] * V[i,d], 2-term (att hi/lo slabs),
// 128(j) x 128(d) block, i-chunks of 32 over slab rows (640).
// smem k-major (stride 136 -> conflict-free fragment reads).
// Fill: thread t covers slab row t>>2, float range (t&3)*32 .. +31.
// Output split into g_y0h/g_y0l.
// =====================================================================
#define AVST 136
#define AVTS (32 * AVST)

__global__ __launch_bounds__(128) void attv2_mma()
{
    extern __shared__ float sm[];
    const int SST = 3 * AVTS;
    float* sAh = sm;
    float* sAl = sm + AVTS;
    float* sV  = sm + 2 * AVTS;

    const int t = threadIdx.x;
    const int warp = t >> 5, lane = t & 31;
    const int g = lane >> 2, tig = lane & 3;
    const int wm = warp >> 1, wn = warp & 1;

    const int jb = blockIdx.y;                 // j block
    const int j0 = jb * 128;
    const int d0 = blockIdx.x * 128;

    const float* slabH = g_AH + (size_t)jb * SLABR * 128;
    const float* slabL = g_AL + (size_t)jb * SLABR * 128;

    // fill mapping: row fr = t>>2 (0..31), float offset fq = (t&3)*32 (full 128/row)
    const int fr = t >> 2;
    const int fq = (t & 3) * 32;
    const uint32_t bAh = s2u(sAh) + (fr * AVST + fq) * 4;
    const uint32_t bAl = s2u(sAl) + (fr * AVST + fq) * 4;
    const uint32_t bV  = s2u(sV)  + (fr * AVST + fq) * 4;

    float acc[4][8][4] = {};

    auto issue = [&](int kt, int s) {
        const int srow = kt * 32 + fr;                   // slab row
        const int iv = j0 - 256 + srow;                  // global i for V
        const bool ok = ((unsigned)iv < (unsigned)NTOK);
        const int ivc = ok ? iv : 0;
        const uint32_t so = (uint32_t)s * SST * 4;
        const float* pH = slabH + (size_t)srow * 128 + fq;
        const float* pL = slabL + (size_t)srow * 128 + fq;
        const float* pV = g_V + (size_t)ivc * DDIM + d0 + fq;
        #pragma unroll
        for (int u = 0; u < 8; u++) {
            cpa16 (bAh + so + u * 16, pH + u * 4);
            cpa16 (bAl + so + u * 16, pL + u * 4);
            cpa16p(bV  + so + u * 16, pV + u * 4, ok);
        }
    };

    const int KT = SLABR / 32;   // 20
    issue(0, 0);
    CPA_COMMIT();

    for (int kt = 0; kt < KT; kt++) {
        const int s = kt & 1;
        if (kt + 1 < KT) issue(kt + 1, s ^ 1);
        CPA_COMMIT();
        CPA_WAIT1();
        __syncthreads();

        const float* pAh = sAh + s * SST;
        const float* pAl = sAl + s * SST;
        const float* pV  = sV  + s * SST;

        #pragma unroll
        for (int k8 = 0; k8 < 4; k8++) {
            const int kk = k8 * 8 + tig;
            const int r0 = kk * AVST;
            const int r1 = (kk + 4) * AVST;
            float ah[4][4], al[4][4], bv[8][2];
            #pragma unroll
            for (int fm = 0; fm < 4; fm++) {
                const int m = wm * 64 + fm * 16 + g;
                ah[fm][0] = pAh[r0 + m];      ah[fm][1] = pAh[r0 + m + 8];
                ah[fm][2] = pAh[r1 + m];      ah[fm][3] = pAh[r1 + m + 8];
                al[fm][0] = pAl[r0 + m];      al[fm][1] = pAl[r0 + m + 8];
                al[fm][2] = pAl[r1 + m];      al[fm][3] = pAl[r1 + m + 8];
            }
            #pragma unroll
            for (int fn = 0; fn < 8; fn++) {
                const int n = wn * 64 + fn * 8 + g;
                bv[fn][0] = pV[r0 + n];
                bv[fn][1] = pV[r1 + n];
            }
            #pragma unroll
            for (int fm = 0; fm < 4; fm++)
                #pragma unroll
                for (int fn = 0; fn < 8; fn++) {
                    mma_tf32(acc[fm][fn], ah[fm], bv[fn]);
                    mma_tf32(acc[fm][fn], al[fm], bv[fn]);
                }
        }
        __syncthreads();
    }

    #pragma unroll
    for (int fm = 0; fm < 4; fm++) {
        #pragma unroll
        for (int half = 0; half < 2; half++) {
            const int j = j0 + wm * 64 + fm * 16 + g + half * 8;
            #pragma unroll
            for (int fn = 0; fn < 8; fn++) {
                const int d = d0 + wn * 64 + fn * 8 + 2 * tig;
                const size_t base = (size_t)j * DDIM + d;
                #pragma unroll
                for (int c = 0; c < 2; c++) {
                    const float v = acc[fm][fn][half * 2 + c];
                    const float h = tf32f(v);
                    g_y0h[base + c] = h;
                    g_y0l[base + c] = tf32f(v - h);
                }
            }
        }
    }
}

// =====================================================================
extern "C" void kernel_launch(void* const* d_in, const int* in_sizes, int n_in,
                              void* d_out, int out_size)
{
    const float* x  = (const float*)d_in[0];
    const float* Wq = (const float*)d_in[1];
    const float* Wk = (const float*)d_in[2];
    const float* Wv = (const float*)d_in[3];
    const float* Wo = (const float*)d_in[4];

    float *xh, *xl, *wq, *wk, *wv, *wo, *qh, *ql, *kh, *kl, *vp, *y0h, *y0l;
    cudaGetSymbolAddress((void**)&xh,  g_xh);
    cudaGetSymbolAddress((void**)&xl,  g_xl);
    cudaGetSymbolAddress((void**)&wq,  g_Wq);
    cudaGetSymbolAddress((void**)&wk,  g_Wk);
    cudaGetSymbolAddress((void**)&wv,  g_Wv);
    cudaGetSymbolAddress((void**)&wo,  g_Wo);
    cudaGetSymbolAddress((void**)&qh,  g_Qh);
    cudaGetSymbolAddress((void**)&ql,  g_Ql);
    cudaGetSymbolAddress((void**)&kh,  g_Kh);
    cudaGetSymbolAddress((void**)&kl,  g_Kl);
    cudaGetSymbolAddress((void**)&vp,  g_V);
    cudaGetSymbolAddress((void**)&y0h, g_y0h);
    cudaGetSymbolAddress((void**)&y0l, g_y0l);

    const size_t yel = (size_t)NTOK * DDIM;
    const size_t ael = (size_t)NTOK * NTOK;
    float* d_y;
    float* d_att;
    int write_att;
    if ((size_t)out_size >= yel + ael) {
        d_y = (float*)d_out;
        d_att = (float*)d_out + yel;
        write_att = 1;
    } else if ((size_t)out_size >= ael) {
        d_y = qh;
        d_att = (float*)d_out;
        write_att = 1;
    } else {
        d_y = (float*)d_out;
        d_att = nullptr;
        write_att = 0;
    }

    // dynamic smem opt-in (not stream ops; capture-safe)
    const int smem2  = 2 * 3 * MTS * 4;        // 96 KB  (2-term engine)
    const int smemQK = 2 * 4 * MTS * 4;        // 128 KB (qk 3-term)
    const int smemAV = 2 * 3 * AVTS * 4;       // ~102 KB (attv)
    cudaFuncSetAttribute(gemm2<1,0>, cudaFuncAttributeMaxDynamicSharedMemorySize, smem2);
    cudaFuncSetAttribute(gemm2<1,1>, cudaFuncAttributeMaxDynamicSharedMemorySize, smem2);
    cudaFuncSetAttribute(gemm2<1,2>, cudaFuncAttributeMaxDynamicSharedMemorySize, smem2);
    cudaFuncSetAttribute(qk3_mma,    cudaFuncAttributeMaxDynamicSharedMemorySize, smemQK);
    cudaFuncSetAttribute(attv2_mma,  cudaFuncAttributeMaxDynamicSharedMemorySize, smemAV);

    const int n1 = NTOK * DDIM;
    const int n2 = DDIM * DDIM;
    split_k<<<n1 / 256, 256>>>(x, xh, xl, n1);
    round_k<<<n2 / 256, 256>>>(Wq, wq, n2);
    round_k<<<n2 / 256, 256>>>(Wk, wk, n2);
    round_k<<<n2 / 256, 256>>>(Wv, wv, n2);
    round_k<<<n2 / 256, 256>>>(Wo, wo, n2);

    const dim3 gP(DDIM / 128, NTOK / 128);     // (8, 64)

    // Q, K: 2-term (x split, W rounded), outputs split hi/lo for band stage
    gemm2<1,2><<<gP, 128, smem2>>>(xh, xl, wq, qh, ql, NTOK, DDIM, DDIM, 0.06f);
    gemm2<1,2><<<gP, 128, smem2>>>(xh, xl, wk, kh, kl, NTOK, DDIM, DDIM, 1.0f);
    // V: 2-term, output tf32-rounded for attv
    gemm2<1,1><<<gP, 128, smem2>>>(xh, xl, wv, vp, nullptr, NTOK, DDIM, DDIM, 1.0f);

    // banded logits, 3-term exact on split Q/K
    qk3_mma<<<dim3(5, NTOK / 128), 128, smemQK>>>();

    if (write_att)
        cudaMemsetAsync(d_att, 0, ael * sizeof(float));
    softmax_band_kernel<<<NTOK, 256>>>(d_att, write_att);

    // y0 = att^T @ V (2-term att), split output
    attv2_mma<<<dim3(DDIM / 128, NTOK / 128), 128, smemAV>>>();

    // y = y0 @ Wo^T (2-term y0)
    gemm2<1,0><<<gP, 128, smem2>>>(y0h, y0l, wo, d_y, nullptr, NTOK, DDIM, DDIM, 1.0f);
}

// round 7
// speedup vs baseline: 1.3156x; 1.3156x over previous
#include <cuda_runtime.h>
#include <math.h>
#include <stdint.h>

#define NTOK 8192
#define DDIM 1024
#define APW  249            // band: |i-j| <= 249
#define BANDW 512           // raw logits band stride
#define NSLAB (NTOK / 128)  // 64 j-blocks
#define SLABR 640           // slab rows: i in [jb*128-256, jb*128+384)

// ---------------- scratch (static device arrays; zero-initialized) ----------------
__device__ float g_xh [(size_t)NTOK * DDIM];
__device__ float g_xl [(size_t)NTOK * DDIM];
__device__ float g_Wq [DDIM * DDIM];
__device__ float g_Wk [DDIM * DDIM];
__device__ float g_Wv [DDIM * DDIM];
__device__ float g_Wo [DDIM * DDIM];
__device__ float g_Qh [(size_t)NTOK * DDIM];
__device__ float g_Ql [(size_t)NTOK * DDIM];
__device__ float g_Kh [(size_t)NTOK * DDIM];
__device__ float g_Kl [(size_t)NTOK * DDIM];
__device__ float g_V  [(size_t)NTOK * DDIM];               // tf32-rounded
__device__ float g_S  [(size_t)NTOK * BANDW];              // raw logits band
__device__ float g_AH [(size_t)NSLAB * SLABR * 128];       // att hi slabs
__device__ float g_AL [(size_t)NSLAB * SLABR * 128];       // att lo slabs
__device__ float g_y0h[(size_t)NTOK * DDIM];
__device__ float g_y0l[(size_t)NTOK * DDIM];

// ---------------- helpers ----------------
__device__ __forceinline__ uint32_t f2tf32(float f) {
    uint32_t u;
    asm("cvt.rna.tf32.f32 %0, %1;" : "=r"(u) : "f"(f));
    return u;
}
__device__ __forceinline__ float tf32f(float f) { return __uint_as_float(f2tf32(f)); }

__device__ __forceinline__ void mma_tf32(float c[4], const float a[4], const float b[2]) {
    asm volatile(
        "mma.sync.aligned.m16n8k8.row.col.f32.tf32.tf32.f32 "
        "{%0,%1,%2,%3}, {%4,%5,%6,%7}, {%8,%9}, {%0,%1,%2,%3};"
        : "+f"(c[0]), "+f"(c[1]), "+f"(c[2]), "+f"(c[3])
        : "r"(__float_as_uint(a[0])), "r"(__float_as_uint(a[1])),
          "r"(__float_as_uint(a[2])), "r"(__float_as_uint(a[3])),
          "r"(__float_as_uint(b[0])), "r"(__float_as_uint(b[1])));
}

__device__ __forceinline__ uint32_t s2u(const void* p) {
    return (uint32_t)__cvta_generic_to_shared(p);
}
__device__ __forceinline__ void cpa16(uint32_t dst, const float* src) {
    asm volatile("cp.async.cg.shared.global [%0], [%1], 16;" :: "r"(dst), "l"(src));
}
__device__ __forceinline__ void cpa16p(uint32_t dst, const float* src, bool ok) {
    int sz = ok ? 16 : 0;
    asm volatile("cp.async.cg.shared.global [%0], [%1], 16, %2;" :: "r"(dst), "l"(src), "r"(sz));
}
#define CPA_COMMIT() asm volatile("cp.async.commit_group;")
template<int N> __device__ __forceinline__ void cpa_wait() {
    asm volatile("cp.async.wait_group %0;" :: "n"(N));
}

// ---------------- prep: split / round ----------------
__global__ void split_k(const float* __restrict__ src, float* __restrict__ hi,
                        float* __restrict__ lo, int n) {
    int i = blockIdx.x * blockDim.x + threadIdx.x;
    if (i < n) {
        float v = src[i];
        float h = tf32f(v);
        hi[i] = h;
        lo[i] = tf32f(v - h);
    }
}
__global__ void round_k(const float* __restrict__ src, float* __restrict__ dst, int n) {
    int i = blockIdx.x * blockDim.x + threadIdx.x;
    if (i < n) dst[i] = tf32f(src[i]);
}

// =====================================================================
// Engine v3: C = alpha * (Ah+Al) @ B^T, row-major, tf32 mma.
// 128x128 block, 256 threads = 8 warps, warp tile 64x32.
// 4-stage cp.async pipeline, BK=16 per stage.
// smem row = 16 floats (64B = 4 x 16B chunks), chunk swizzle c^((row>>1)&3).
// OUT: 0 = fp32, 1 = tf32-rounded, 2 = split (C=hi, C2=lo)
// =====================================================================
#define BKS  16
#define MSTG (128 * BKS)      // 2048 floats per matrix-stage
#define STG  4                // pipeline stages

template<int AL, int OUT>
__global__ __launch_bounds__(256, 2) void gemm3(
    const float* __restrict__ Ah, const float* __restrict__ Al,
    const float* __restrict__ B,
    float* __restrict__ C, float* __restrict__ C2,
    int M, int N, int K, float alpha)
{
    extern __shared__ float sm[];
    const int NM = AL ? 3 : 2;

    const int t = threadIdx.x;
    const int warp = t >> 5, lane = t & 31;
    const int g = lane >> 2, tig = lane & 3;
    const int wm = warp >> 2, wn = warp & 3;          // 2 x 64 rows, 4 x 32 cols

    const int rowA0 = blockIdx.y * 128;
    const int rowB0 = blockIdx.x * 128;

    // fill mapping: row fr = t>>1, logical chunks fc, fc+1 (fc = (t&1)*2)
    const int fr  = t >> 1;
    const int fc  = (t & 1) * 2;
    const int fsw = (fr >> 1) & 3;
    const float* gA  = Ah + (size_t)(rowA0 + fr) * K + fc * 4;
    const float* gA2 = AL ? (Al + (size_t)(rowA0 + fr) * K + fc * 4) : gA;
    const float* gB  = B  + (size_t)(rowB0 + fr) * K + fc * 4;

    const uint32_t base = s2u(sm);
    const uint32_t d0 = (uint32_t)(fr * 64 + ((fc    ) ^ fsw) * 16);
    const uint32_t d1 = (uint32_t)(fr * 64 + ((fc + 1) ^ fsw) * 16);

    const int fth = (g >> 1) & 3;                      // fragment-read swizzle key

    float acc[4][4][4] = {};

    auto issue = [&](int kt, int s) {
        const uint32_t sb = base + (uint32_t)(s * NM) * (MSTG * 4);
        const float* pa  = gA  + kt * BKS;
        const float* pb  = gB  + kt * BKS;
        cpa16(sb + d0, pa);  cpa16(sb + d1, pa + 4);
        if (AL) {
            const float* pa2 = gA2 + kt * BKS;
            cpa16(sb + MSTG * 4 + d0, pa2);  cpa16(sb + MSTG * 4 + d1, pa2 + 4);
        }
        const uint32_t bo = (uint32_t)(AL ? 2 : 1) * (MSTG * 4);
        cpa16(sb + bo + d0, pb);  cpa16(sb + bo + d1, pb + 4);
    };

    const int KT = K / BKS;
    #pragma unroll
    for (int p = 0; p < STG - 1; p++) { issue(p, p); CPA_COMMIT(); }

    for (int kt = 0; kt < KT; kt++) {
        const int s = kt & (STG - 1);
        cpa_wait<STG - 2>();
        __syncthreads();
        const int nk = kt + STG - 1;
        if (nk < KT) issue(nk, nk & (STG - 1));
        CPA_COMMIT();

        const float* pA  = sm + (s * NM) * MSTG;
        const float* pA2 = pA + MSTG;
        const float* pB  = pA + (AL ? 2 : 1) * MSTG;

        #pragma unroll
        for (int s8 = 0; s8 < 2; s8++) {
            const int olo = 4 * ((2 * s8    ) ^ fth) + tig;
            const int ohi = 4 * ((2 * s8 + 1) ^ fth) + tig;
            float a[4][4], a2[4][4], b[4][2];
            #pragma unroll
            for (int fm = 0; fm < 4; fm++) {
                const int m = (wm * 64 + fm * 16 + g) * BKS;
                a[fm][0] = pA[m + olo];          a[fm][1] = pA[m + 8 * BKS + olo];
                a[fm][2] = pA[m + ohi];          a[fm][3] = pA[m + 8 * BKS + ohi];
                if (AL) {
                    a2[fm][0] = pA2[m + olo];    a2[fm][1] = pA2[m + 8 * BKS + olo];
                    a2[fm][2] = pA2[m + ohi];    a2[fm][3] = pA2[m + 8 * BKS + ohi];
                }
            }
            #pragma unroll
            for (int fn = 0; fn < 4; fn++) {
                const int n = (wn * 32 + fn * 8 + g) * BKS;
                b[fn][0] = pB[n + olo];
                b[fn][1] = pB[n + ohi];
            }
            #pragma unroll
            for (int fm = 0; fm < 4; fm++)
                #pragma unroll
                for (int fn = 0; fn < 4; fn++) {
                    mma_tf32(acc[fm][fn], a[fm], b[fn]);
                    if (AL) mma_tf32(acc[fm][fn], a2[fm], b[fn]);
                }
        }
    }

    #pragma unroll
    for (int fm = 0; fm < 4; fm++) {
        #pragma unroll
        for (int half = 0; half < 2; half++) {
            const int m0 = rowA0 + wm * 64 + fm * 16 + g + half * 8;
            #pragma unroll
            for (int fn = 0; fn < 4; fn++) {
                const int n0 = rowB0 + wn * 32 + fn * 8 + 2 * tig;
                const size_t bidx = (size_t)m0 * N + n0;
                #pragma unroll
                for (int c = 0; c < 2; c++) {
                    float v = alpha * acc[fm][fn][half * 2 + c];
                    if (OUT == 0) C[bidx + c] = v;
                    else if (OUT == 1) C[bidx + c] = tf32f(v);
                    else {
                        float h = tf32f(v);
                        C[bidx + c]  = h;
                        C2[bidx + c] = tf32f(v - h);
                    }
                }
            }
        }
    }
}

// =====================================================================
// Banded logits, 3-term on pre-split operands (hh + hl + lh).
// Same engine structure; 4 matrices -> 128 KB smem (1 CTA/SM, deep pipe).
// =====================================================================
__global__ __launch_bounds__(256) void qk3_mma()
{
    extern __shared__ float sm[];
    const int NM = 4;

    const int t = threadIdx.x;
    const int warp = t >> 5, lane = t & 31;
    const int g = lane >> 2, tig = lane & 3;
    const int wm = warp >> 2, wn = warp & 3;

    const int i0 = blockIdx.y * 128;
    const int j0 = i0 - APW + (int)blockIdx.x * 128;

    const int fr  = t >> 1;
    const int fc  = (t & 1) * 2;
    const int fsw = (fr >> 1) & 3;

    const int jr = j0 + fr;
    const bool jok = ((unsigned)jr < (unsigned)NTOK);
    const int jrc = jok ? jr : 0;

    const float* gQh = g_Qh + (size_t)(i0 + fr) * DDIM + fc * 4;
    const float* gQl = g_Ql + (size_t)(i0 + fr) * DDIM + fc * 4;
    const float* gKh = g_Kh + (size_t)jrc * DDIM + fc * 4;
    const float* gKl = g_Kl + (size_t)jrc * DDIM + fc * 4;

    const uint32_t base = s2u(sm);
    const uint32_t d0 = (uint32_t)(fr * 64 + ((fc    ) ^ fsw) * 16);
    const uint32_t d1 = (uint32_t)(fr * 64 + ((fc + 1) ^ fsw) * 16);
    const int fth = (g >> 1) & 3;

    float acc[4][4][4] = {};

    auto issue = [&](int kt, int s) {
        const uint32_t sb = base + (uint32_t)(s * NM) * (MSTG * 4);
        const int ko = kt * BKS;
        cpa16 (sb +              d0, gQh + ko);  cpa16 (sb +              d1, gQh + ko + 4);
        cpa16 (sb + 1*MSTG*4 +   d0, gQl + ko);  cpa16 (sb + 1*MSTG*4 +   d1, gQl + ko + 4);
        cpa16p(sb + 2*MSTG*4 +   d0, gKh + ko, jok);  cpa16p(sb + 2*MSTG*4 + d1, gKh + ko + 4, jok);
        cpa16p(sb + 3*MSTG*4 +   d0, gKl + ko, jok);  cpa16p(sb + 3*MSTG*4 + d1, gKl + ko + 4, jok);
    };

    const int KT = DDIM / BKS;
    #pragma unroll
    for (int p = 0; p < STG - 1; p++) { issue(p, p); CPA_COMMIT(); }

    for (int kt = 0; kt < KT; kt++) {
        const int s = kt & (STG - 1);
        cpa_wait<STG - 2>();
        __syncthreads();
        const int nk = kt + STG - 1;
        if (nk < KT) issue(nk, nk & (STG - 1));
        CPA_COMMIT();

        const float* pQh = sm + (s * NM) * MSTG;
        const float* pQl = pQh + MSTG;
        const float* pKh = pQh + 2 * MSTG;
        const float* pKl = pQh + 3 * MSTG;

        #pragma unroll
        for (int s8 = 0; s8 < 2; s8++) {
            const int olo = 4 * ((2 * s8    ) ^ fth) + tig;
            const int ohi = 4 * ((2 * s8 + 1) ^ fth) + tig;
            float ah[4][4], al[4][4], bh[4][2], bl[4][2];
            #pragma unroll
            for (int fm = 0; fm < 4; fm++) {
                const int m = (wm * 64 + fm * 16 + g) * BKS;
                ah[fm][0] = pQh[m + olo];       ah[fm][1] = pQh[m + 8 * BKS + olo];
                ah[fm][2] = pQh[m + ohi];       ah[fm][3] = pQh[m + 8 * BKS + ohi];
                al[fm][0] = pQl[m + olo];       al[fm][1] = pQl[m + 8 * BKS + olo];
                al[fm][2] = pQl[m + ohi];       al[fm][3] = pQl[m + 8 * BKS + ohi];
            }
            #pragma unroll
            for (int fn = 0; fn < 4; fn++) {
                const int n = (wn * 32 + fn * 8 + g) * BKS;
                bh[fn][0] = pKh[n + olo];       bh[fn][1] = pKh[n + ohi];
                bl[fn][0] = pKl[n + olo];       bl[fn][1] = pKl[n + ohi];
            }
            #pragma unroll
            for (int fm = 0; fm < 4; fm++)
                #pragma unroll
                for (int fn = 0; fn < 4; fn++) {
                    mma_tf32(acc[fm][fn], ah[fm], bh[fn]);
                    mma_tf32(acc[fm][fn], ah[fm], bl[fn]);
                    mma_tf32(acc[fm][fn], al[fm], bh[fn]);
                }
        }
    }

    // band-masked store
    #pragma unroll
    for (int fm = 0; fm < 4; fm++) {
        #pragma unroll
        for (int half = 0; half < 2; half++) {
            const int i = i0 + wm * 64 + fm * 16 + g + half * 8;
            #pragma unroll
            for (int fn = 0; fn < 4; fn++) {
                const int jb = j0 + wn * 32 + fn * 8 + 2 * tig;
                #pragma unroll
                for (int c = 0; c < 2; c++) {
                    const int j = jb + c;
                    const int tt = j - i + APW;
                    if ((unsigned)j < (unsigned)NTOK && (unsigned)tt <= (unsigned)(2 * APW))
                        g_S[(size_t)i * BANDW + tt] = acc[fm][fn][half * 2 + c];
                }
            }
        }
    }
}

// =====================================================================
// Per-row band softmax -> d_att (fp32) + att hi/lo SLABS
// slab layout: g_AH[jb][srow][jc], jb=j>>7, srow=i-128*jb+256, jc=j&127
// =====================================================================
__global__ __launch_bounds__(256) void softmax_band_kernel(float* __restrict__ d_att,
                                                           int write_att)
{
    const int i = blockIdx.x;
    const int t = threadIdx.x;
    const int t_lo = (i < APW) ? (APW - i) : 0;
    const int jmax = (i + APW < NTOK - 1) ? (i + APW) : (NTOK - 1);
    const int t_hi = jmax - i + APW;

    const float* row = g_S + (size_t)i * BANDW;
    const int t0 = t, t1 = t + 256;
    float v0 = (t0 >= t_lo && t0 <= t_hi) ? row[t0] : -INFINITY;
    float v1 = (t1 >= t_lo && t1 <= t_hi) ? row[t1] : -INFINITY;

    __shared__ float shm[8];
    __shared__ float shs[8];
    const int lane = t & 31, warp = t >> 5;

    float m = fmaxf(v0, v1);
    #pragma unroll
    for (int o = 16; o > 0; o >>= 1) m = fmaxf(m, __shfl_xor_sync(0xffffffffu, m, o));
    if (lane == 0) shm[warp] = m;
    __syncthreads();
    if (warp == 0) {
        float mm = (lane < 8) ? shm[lane] : -INFINITY;
        #pragma unroll
        for (int o = 4; o > 0; o >>= 1) mm = fmaxf(mm, __shfl_xor_sync(0xffffffffu, mm, o));
        if (lane == 0) shm[0] = mm;
    }
    __syncthreads();
    const float M = shm[0];

    const float e0 = expf(v0 - M);
    const float e1 = expf(v1 - M);
    float s = e0 + e1;
    #pragma unroll
    for (int o = 16; o > 0; o >>= 1) s += __shfl_xor_sync(0xffffffffu, s, o);
    if (lane == 0) shs[warp] = s;
    __syncthreads();
    if (warp == 0) {
        float ss = (lane < 8) ? shs[lane] : 0.f;
        #pragma unroll
        for (int o = 4; o > 0; o >>= 1) ss += __shfl_xor_sync(0xffffffffu, ss, o);
        if (lane == 0) shs[0] = ss;
    }
    __syncthreads();
    const float inv = 1.0f / shs[0];

    #pragma unroll
    for (int q = 0; q < 2; q++) {
        const int tt = q ? t1 : t0;
        const float e = q ? e1 : e0;
        if (tt >= t_lo && tt <= t_hi) {
            const float w = e * inv;
            const int j = i - APW + tt;
            const int jb = j >> 7;
            const size_t sidx = ((size_t)jb * SLABR + (i - jb * 128 + 256)) * 128 + (j & 127);
            const float h = tf32f(w);
            g_AH[sidx] = h;
            g_AL[sidx] = tf32f(w - h);
            if (write_att) d_att[(size_t)i * NTOK + j] = w;
        }
    }
}

// =====================================================================
// attv v3: y0[j,d] = sum_i att[i,j]*V[i,d], 2-term att, tf32 mma.
// 128(j) x 128(d) block, 256 threads, warp tile 64x32.
// k(=i) chunks of 16 slab rows, 4-stage pipeline, k-major smem stride 136.
// =====================================================================
#define AVR  136
#define AVTSS (16 * AVR)          // floats per matrix-stage

__global__ __launch_bounds__(256, 2) void attv3_mma()
{
    extern __shared__ float sm[];
    const int NM = 3;

    const int t = threadIdx.x;
    const int warp = t >> 5, lane = t & 31;
    const int g = lane >> 2, tig = lane & 3;
    const int wm = warp >> 2, wn = warp & 3;

    const int jb = blockIdx.y;
    const int j0 = jb * 128;
    const int d0 = blockIdx.x * 128;

    const float* slabH = g_AH + (size_t)jb * SLABR * 128;
    const float* slabL = g_AL + (size_t)jb * SLABR * 128;

    // fill: row ft = t>>4 (0..15), chunks c = (t&15)*2, +1  -> floats c*4 .. c*4+7
    const int ft = t >> 4;
    const int fq = (t & 15) * 8;
    const uint32_t base = s2u(sm);
    const uint32_t doff = (uint32_t)(ft * AVR + fq) * 4;

    float acc[4][4][4] = {};

    auto issue = [&](int kt, int s) {
        const int srow = kt * 16 + ft;
        const int iv = j0 - 256 + srow;
        const bool ok = ((unsigned)iv < (unsigned)NTOK);
        const int ivc = ok ? iv : 0;
        const uint32_t sb = base + (uint32_t)(s * NM) * (AVTSS * 4) + doff;
        const float* pH = slabH + (size_t)srow * 128 + fq;
        const float* pL = slabL + (size_t)srow * 128 + fq;
        const float* pV = g_V + (size_t)ivc * DDIM + d0 + fq;
        cpa16 (sb, pH);                   cpa16 (sb + 16, pH + 4);
        cpa16 (sb + AVTSS * 4, pL);       cpa16 (sb + AVTSS * 4 + 16, pL + 4);
        cpa16p(sb + 2 * AVTSS * 4, pV, ok); cpa16p(sb + 2 * AVTSS * 4 + 16, pV + 4, ok);
    };

    const int KT = SLABR / 16;    // 40
    #pragma unroll
    for (int p = 0; p < STG - 1; p++) { issue(p, p); CPA_COMMIT(); }

    for (int kt = 0; kt < KT; kt++) {
        const int s = kt & (STG - 1);
        cpa_wait<STG - 2>();
        __syncthreads();
        const int nk = kt + STG - 1;
        if (nk < KT) issue(nk, nk & (STG - 1));
        CPA_COMMIT();

        const float* pAh = sm + (s * NM) * AVTSS;
        const float* pAl = pAh + AVTSS;
        const float* pV  = pAh + 2 * AVTSS;

        #pragma unroll
        for (int s8 = 0; s8 < 2; s8++) {
            const int kk = 8 * s8 + tig;
            const int r0 = kk * AVR;
            const int r1 = (kk + 4) * AVR;
            float ah[4][4], al[4][4], bv[4][2];
            #pragma unroll
            for (int fm = 0; fm < 4; fm++) {
                const int m = wm * 64 + fm * 16 + g;
                ah[fm][0] = pAh[r0 + m];      ah[fm][1] = pAh[r0 + m + 8];
                ah[fm][2] = pAh[r1 + m];      ah[fm][3] = pAh[r1 + m + 8];
                al[fm][0] = pAl[r0 + m];      al[fm][1] = pAl[r0 + m + 8];
                al[fm][2] = pAl[r1 + m];      al[fm][3] = pAl[r1 + m + 8];
            }
            #pragma unroll
            for (int fn = 0; fn < 4; fn++) {
                const int n = wn * 32 + fn * 8 + g;
                bv[fn][0] = pV[r0 + n];
                bv[fn][1] = pV[r1 + n];
            }
            #pragma unroll
            for (int fm = 0; fm < 4; fm++)
                #pragma unroll
                for (int fn = 0; fn < 4; fn++) {
                    mma_tf32(acc[fm][fn], ah[fm], bv[fn]);
                    mma_tf32(acc[fm][fn], al[fm], bv[fn]);
                }
        }
    }

    #pragma unroll
    for (int fm = 0; fm < 4; fm++) {
        #pragma unroll
        for (int half = 0; half < 2; half++) {
            const int j = j0 + wm * 64 + fm * 16 + g + half * 8;
            #pragma unroll
            for (int fn = 0; fn < 4; fn++) {
                const int d = d0 + wn * 32 + fn * 8 + 2 * tig;
                const size_t bidx = (size_t)j * DDIM + d;
                #pragma unroll
                for (int c = 0; c < 2; c++) {
                    const float v = acc[fm][fn][half * 2 + c];
                    const float h = tf32f(v);
                    g_y0h[bidx + c] = h;
                    g_y0l[bidx + c] = tf32f(v - h);
                }
            }
        }
    }
}

// =====================================================================
extern "C" void kernel_launch(void* const* d_in, const int* in_sizes, int n_in,
                              void* d_out, int out_size)
{
    const float* x  = (const float*)d_in[0];
    const float* Wq = (const float*)d_in[1];
    const float* Wk = (const float*)d_in[2];
    const float* Wv = (const float*)d_in[3];
    const float* Wo = (const float*)d_in[4];

    float *xh, *xl, *wq, *wk, *wv, *wo, *qh, *ql, *kh, *kl, *vp, *y0h, *y0l;
    cudaGetSymbolAddress((void**)&xh,  g_xh);
    cudaGetSymbolAddress((void**)&xl,  g_xl);
    cudaGetSymbolAddress((void**)&wq,  g_Wq);
    cudaGetSymbolAddress((void**)&wk,  g_Wk);
    cudaGetSymbolAddress((void**)&wv,  g_Wv);
    cudaGetSymbolAddress((void**)&wo,  g_Wo);
    cudaGetSymbolAddress((void**)&qh,  g_Qh);
    cudaGetSymbolAddress((void**)&ql,  g_Ql);
    cudaGetSymbolAddress((void**)&kh,  g_Kh);
    cudaGetSymbolAddress((void**)&kl,  g_Kl);
    cudaGetSymbolAddress((void**)&vp,  g_V);
    cudaGetSymbolAddress((void**)&y0h, g_y0h);
    cudaGetSymbolAddress((void**)&y0l, g_y0l);

    const size_t yel = (size_t)NTOK * DDIM;
    const size_t ael = (size_t)NTOK * NTOK;
    float* d_y;
    float* d_att;
    int write_att;
    if ((size_t)out_size >= yel + ael) {
        d_y = (float*)d_out;
        d_att = (float*)d_out + yel;
        write_att = 1;
    } else if ((size_t)out_size >= ael) {
        d_y = qh;
        d_att = (float*)d_out;
        write_att = 1;
    } else {
        d_y = (float*)d_out;
        d_att = nullptr;
        write_att = 0;
    }

    // dynamic smem opt-in (not stream ops; capture-safe)
    const int smemG  = STG * 3 * MSTG * 4;     // 96 KB
    const int smemQK = STG * 4 * MSTG * 4;     // 128 KB
    const int smemAV = STG * 3 * AVTSS * 4;    // ~102 KB
    cudaFuncSetAttribute(gemm3<1,0>, cudaFuncAttributeMaxDynamicSharedMemorySize, smemG);
    cudaFuncSetAttribute(gemm3<1,1>, cudaFuncAttributeMaxDynamicSharedMemorySize, smemG);
    cudaFuncSetAttribute(gemm3<1,2>, cudaFuncAttributeMaxDynamicSharedMemorySize, smemG);
    cudaFuncSetAttribute(qk3_mma,    cudaFuncAttributeMaxDynamicSharedMemorySize, smemQK);
    cudaFuncSetAttribute(attv3_mma,  cudaFuncAttributeMaxDynamicSharedMemorySize, smemAV);

    const int n1 = NTOK * DDIM;
    const int n2 = DDIM * DDIM;
    split_k<<<n1 / 256, 256>>>(x, xh, xl, n1);
    round_k<<<n2 / 256, 256>>>(Wq, wq, n2);
    round_k<<<n2 / 256, 256>>>(Wk, wk, n2);
    round_k<<<n2 / 256, 256>>>(Wv, wv, n2);
    round_k<<<n2 / 256, 256>>>(Wo, wo, n2);

    const dim3 gP(DDIM / 128, NTOK / 128);     // (8, 64)

    // Q, K: 2-term (x split, W rounded), outputs split hi/lo for band stage
    gemm3<1,2><<<gP, 256, smemG>>>(xh, xl, wq, qh, ql, NTOK, DDIM, DDIM, 0.06f);
    gemm3<1,2><<<gP, 256, smemG>>>(xh, xl, wk, kh, kl, NTOK, DDIM, DDIM, 1.0f);
    // V: 2-term, output tf32-rounded for attv
    gemm3<1,1><<<gP, 256, smemG>>>(xh, xl, wv, vp, nullptr, NTOK, DDIM, DDIM, 1.0f);

    // banded logits, 3-term exact on split Q/K
    qk3_mma<<<dim3(5, NTOK / 128), 256, smemQK>>>();

    if (write_att)
        cudaMemsetAsync(d_att, 0, ael * sizeof(float));
    softmax_band_kernel<<<NTOK, 256>>>(d_att, write_att);

    // y0 = att^T @ V (2-term att), split output
    attv3_mma<<<dim3(DDIM / 128, NTOK / 128), 256, smemAV>>>();

    // y = y0 @ Wo^T (2-term y0)
    gemm3<1,0><<<gP, 256, smemG>>>(y0h, y0l, wo, d_y, nullptr, NTOK, DDIM, DDIM, 1.0f);
}

// round 9
// speedup vs baseline: 1.8552x; 1.4102x over previous
#include <cuda_runtime.h>
#include <cuda_bf16.h>
#include <math.h>
#include <stdint.h>

#define NTOK 8192
#define DDIM 1024
#define APW  249            // band: |i-j| <= 249
#define BANDW 512           // raw logits band stride
#define NSLAB (NTOK / 128)  // 64 j-blocks
#define SLABR 640           // slab rows: i in [jb*128-256, jb*128+384)

// ---------------- scratch (static device arrays; zero-initialized) ----------------
__device__ __nv_bfloat16 g_xhb[(size_t)NTOK * DDIM];
__device__ __nv_bfloat16 g_xlb[(size_t)NTOK * DDIM];
__device__ __nv_bfloat16 g_Wbf[(size_t)8 * DDIM * DDIM];   // qh,ql,kh,kl,vh,vl,oh,ol
__device__ __nv_bfloat16 g_Qhb[(size_t)NTOK * DDIM];
__device__ __nv_bfloat16 g_Qlb[(size_t)NTOK * DDIM];
__device__ __nv_bfloat16 g_Khb[(size_t)NTOK * DDIM];
__device__ __nv_bfloat16 g_Klb[(size_t)NTOK * DDIM];
__device__ float g_V  [(size_t)NTOK * DDIM];               // tf32-rounded (for tf32 attv)
__device__ float g_S  [(size_t)NTOK * BANDW];              // raw logits band
__device__ float g_AH [(size_t)NSLAB * SLABR * 128];       // att hi slabs (tf32)
__device__ float g_AL [(size_t)NSLAB * SLABR * 128];       // att lo slabs
__device__ __nv_bfloat16 g_y0hb[(size_t)NTOK * DDIM];      // y0 bf16 hi
__device__ __nv_bfloat16 g_y0lb[(size_t)NTOK * DDIM];      // y0 bf16 lo

// ---------------- helpers ----------------
__device__ __forceinline__ uint32_t f2tf32(float f) {
    uint32_t u;
    asm("cvt.rna.tf32.f32 %0, %1;" : "=r"(u) : "f"(f));
    return u;
}
__device__ __forceinline__ float tf32f(float f) { return __uint_as_float(f2tf32(f)); }

__device__ __forceinline__ void mma_tf32(float c[4], const float a[4], const float b[2]) {
    asm volatile(
        "mma.sync.aligned.m16n8k8.row.col.f32.tf32.tf32.f32 "
        "{%0,%1,%2,%3}, {%4,%5,%6,%7}, {%8,%9}, {%0,%1,%2,%3};"
        : "+f"(c[0]), "+f"(c[1]), "+f"(c[2]), "+f"(c[3])
        : "r"(__float_as_uint(a[0])), "r"(__float_as_uint(a[1])),
          "r"(__float_as_uint(a[2])), "r"(__float_as_uint(a[3])),
          "r"(__float_as_uint(b[0])), "r"(__float_as_uint(b[1])));
}

__device__ __forceinline__ void mma_bf16(float c[4], const uint32_t a[4], const uint32_t b[2]) {
    asm volatile(
        "mma.sync.aligned.m16n8k16.row.col.f32.bf16.bf16.f32 "
        "{%0,%1,%2,%3}, {%4,%5,%6,%7}, {%8,%9}, {%0,%1,%2,%3};"
        : "+f"(c[0]), "+f"(c[1]), "+f"(c[2]), "+f"(c[3])
        : "r"(a[0]), "r"(a[1]), "r"(a[2]), "r"(a[3]), "r"(b[0]), "r"(b[1]));
}

__device__ __forceinline__ uint32_t s2u(const void* p) {
    return (uint32_t)__cvta_generic_to_shared(p);
}
__device__ __forceinline__ void cpa16(uint32_t dst, const void* src) {
    asm volatile("cp.async.cg.shared.global [%0], [%1], 16;" :: "r"(dst), "l"(src));
}
__device__ __forceinline__ void cpa16p(uint32_t dst, const void* src, bool ok) {
    int sz = ok ? 16 : 0;
    asm volatile("cp.async.cg.shared.global [%0], [%1], 16, %2;" :: "r"(dst), "l"(src), "r"(sz));
}
#define CPA_COMMIT() asm volatile("cp.async.commit_group;")
template<int N> __device__ __forceinline__ void cpa_wait() {
    asm volatile("cp.async.wait_group %0;" :: "n"(N));
}

// ---------------- prep: bf16 hi/lo split ----------------
__global__ void split_bf16_k(const float* __restrict__ src,
                             __nv_bfloat16* __restrict__ hi,
                             __nv_bfloat16* __restrict__ lo, int n) {
    int i = blockIdx.x * blockDim.x + threadIdx.x;
    if (i < n) {
        float v = src[i];
        __nv_bfloat16 h = __float2bfloat16(v);
        hi[i] = h;
        lo[i] = __float2bfloat16(v - __bfloat162float(h));
    }
}

// =====================================================================
// bf16 3-term engine: C = alpha * (Ah+Al)[M,1024] @ (Bh+Bl)[N,1024]^T
// terms hh + hl + lh via mma.sync.m16n8k16 (fp32 accum).
// 128x128 CTA, 256 thr = 8 warps, warp tile 64x32.
// smem: rows of 32 bf16 (64B = 4 x 16B chunks), chunk swizzle c^((row>>1)&3).
// 3-stage cp.async pipeline; 4 matrices/stage (Ah,Al,Bh,Bl) = 32KB/stage.
// OUT: 0 = fp32, 1 = tf32-rounded fp32, 2 = bf16 split (Cbh/Cbl)
// =====================================================================
#define PKC  32                 // k per chunk (bf16 elements)
#define MATW 2048               // u32 words per matrix-stage (128 rows * 16)
#define PSTG 3
#define PG_SMEM (PSTG * 4 * MATW * 4)   // 98304 B

template<int OUT>
__global__ __launch_bounds__(256, 2) void pg_bf16(
    const __nv_bfloat16* __restrict__ Ah, const __nv_bfloat16* __restrict__ Al,
    const __nv_bfloat16* __restrict__ Bh, const __nv_bfloat16* __restrict__ Bl,
    float* __restrict__ Cf, __nv_bfloat16* __restrict__ Cbh,
    __nv_bfloat16* __restrict__ Cbl, float alpha)
{
    extern __shared__ uint32_t smw[];

    const int t = threadIdx.x;
    const int warp = t >> 5, lane = t & 31;
    const int g = lane >> 2, tig = lane & 3;
    const int wm = warp >> 2, wn = warp & 3;
    const int fth = g >> 1;

    const int rowA0 = blockIdx.y * 128;
    const int rowB0 = blockIdx.x * 128;

    // fill mapping: row fr = t>>1, chunks {fc, fc+1}, fc = (t&1)*2
    const int fr  = t >> 1;
    const int fc  = (t & 1) * 2;
    const int fsw = (fr >> 1) & 3;
    const __nv_bfloat16* gAh = Ah + (size_t)(rowA0 + fr) * DDIM + fc * 8;
    const __nv_bfloat16* gAl = Al + (size_t)(rowA0 + fr) * DDIM + fc * 8;
    const __nv_bfloat16* gBh = Bh + (size_t)(rowB0 + fr) * DDIM + fc * 8;
    const __nv_bfloat16* gBl = Bl + (size_t)(rowB0 + fr) * DDIM + fc * 8;

    const uint32_t base = s2u(smw);
    const uint32_t d0 = (uint32_t)(fr * 64 + ((fc    ) ^ fsw) * 16);
    const uint32_t d1 = (uint32_t)(fr * 64 + ((fc + 1) ^ fsw) * 16);

    float acc[4][4][4] = {};

    auto issue = [&](int kt, int s) {
        const uint32_t sb = base + (uint32_t)s * (4 * MATW * 4);
        const int ko = kt * PKC;
        cpa16(sb +               d0, gAh + ko);  cpa16(sb +               d1, gAh + ko + 8);
        cpa16(sb + 1*MATW*4 +    d0, gAl + ko);  cpa16(sb + 1*MATW*4 +    d1, gAl + ko + 8);
        cpa16(sb + 2*MATW*4 +    d0, gBh + ko);  cpa16(sb + 2*MATW*4 +    d1, gBh + ko + 8);
        cpa16(sb + 3*MATW*4 +    d0, gBl + ko);  cpa16(sb + 3*MATW*4 +    d1, gBl + ko + 8);
    };

    const int KT = DDIM / PKC;   // 32
    issue(0, 0); CPA_COMMIT();
    issue(1, 1); CPA_COMMIT();

    for (int kt = 0; kt < KT; kt++) {
        const int s = kt % PSTG;
        cpa_wait<1>();
        __syncthreads();
        const int nk = kt + 2;
        if (nk < KT) issue(nk, nk % PSTG);
        CPA_COMMIT();

        const uint32_t* pAh = smw + s * (4 * MATW);
        const uint32_t* pAl = pAh + MATW;
        const uint32_t* pBh = pAh + 2 * MATW;
        const uint32_t* pBl = pAh + 3 * MATW;

        #pragma unroll
        for (int s8 = 0; s8 < 2; s8++) {
            const int wlo = 4 * ((2 * s8    ) ^ fth) + tig;
            const int whi = 4 * ((2 * s8 + 1) ^ fth) + tig;
            uint32_t bh[4][2], bl[4][2];
            #pragma unroll
            for (int fn = 0; fn < 4; fn++) {
                const int n = (wn * 32 + fn * 8 + g) * 16;
                bh[fn][0] = pBh[n + wlo];   bh[fn][1] = pBh[n + whi];
                bl[fn][0] = pBl[n + wlo];   bl[fn][1] = pBl[n + whi];
            }
            #pragma unroll
            for (int fm = 0; fm < 4; fm++) {
                const int m = (wm * 64 + fm * 16 + g) * 16;
                uint32_t ah[4], al[4];
                ah[0] = pAh[m + wlo];          ah[1] = pAh[m + 128 + wlo];  // +8 rows * 16
                ah[2] = pAh[m + whi];          ah[3] = pAh[m + 128 + whi];
                al[0] = pAl[m + wlo];          al[1] = pAl[m + 128 + wlo];
                al[2] = pAl[m + whi];          al[3] = pAl[m + 128 + whi];
                #pragma unroll
                for (int fn = 0; fn < 4; fn++) {
                    mma_bf16(acc[fm][fn], ah, bh[fn]);
                    mma_bf16(acc[fm][fn], ah, bl[fn]);
                    mma_bf16(acc[fm][fn], al, bh[fn]);
                }
            }
        }
    }

    // epilogue
    #pragma unroll
    for (int fm = 0; fm < 4; fm++) {
        #pragma unroll
        for (int half = 0; half < 2; half++) {
            const int m0 = rowA0 + wm * 64 + fm * 16 + g + half * 8;
            #pragma unroll
            for (int fn = 0; fn < 4; fn++) {
                const int n0 = rowB0 + wn * 32 + fn * 8 + 2 * tig;
                const size_t idx = (size_t)m0 * DDIM + n0;
                float v0 = alpha * acc[fm][fn][half * 2 + 0];
                float v1 = alpha * acc[fm][fn][half * 2 + 1];
                if (OUT == 0) {
                    *(float2*)(Cf + idx) = make_float2(v0, v1);
                } else if (OUT == 1) {
                    *(float2*)(Cf + idx) = make_float2(tf32f(v0), tf32f(v1));
                } else {
                    __nv_bfloat16 h0 = __float2bfloat16(v0);
                    __nv_bfloat16 h1 = __float2bfloat16(v1);
                    __nv_bfloat162 hv; hv.x = h0; hv.y = h1;
                    __nv_bfloat162 lv;
                    lv.x = __float2bfloat16(v0 - __bfloat162float(h0));
                    lv.y = __float2bfloat16(v1 - __bfloat162float(h1));
                    *(__nv_bfloat162*)(Cbh + idx) = hv;
                    *(__nv_bfloat162*)(Cbl + idx) = lv;
                }
            }
        }
    }
}

// =====================================================================
// Banded logits: 3-term bf16 on split Q/K -> g_S (float band).
// Same engine; B (K) rows predicated; band-masked store.
// =====================================================================
__global__ __launch_bounds__(256, 2) void qk_bf16()
{
    extern __shared__ uint32_t smw[];

    const int t = threadIdx.x;
    const int warp = t >> 5, lane = t & 31;
    const int g = lane >> 2, tig = lane & 3;
    const int wm = warp >> 2, wn = warp & 3;
    const int fth = g >> 1;

    const int i0 = blockIdx.y * 128;
    const int j0 = i0 - APW + (int)blockIdx.x * 128;

    const int fr  = t >> 1;
    const int fc  = (t & 1) * 2;
    const int fsw = (fr >> 1) & 3;

    const int jr = j0 + fr;
    const bool jok = ((unsigned)jr < (unsigned)NTOK);
    const int jrc = jok ? jr : 0;

    const __nv_bfloat16* gQh = g_Qhb + (size_t)(i0 + fr) * DDIM + fc * 8;
    const __nv_bfloat16* gQl = g_Qlb + (size_t)(i0 + fr) * DDIM + fc * 8;
    const __nv_bfloat16* gKh = g_Khb + (size_t)jrc * DDIM + fc * 8;
    const __nv_bfloat16* gKl = g_Klb + (size_t)jrc * DDIM + fc * 8;

    const uint32_t base = s2u(smw);
    const uint32_t d0 = (uint32_t)(fr * 64 + ((fc    ) ^ fsw) * 16);
    const uint32_t d1 = (uint32_t)(fr * 64 + ((fc + 1) ^ fsw) * 16);

    float acc[4][4][4] = {};

    auto issue = [&](int kt, int s) {
        const uint32_t sb = base + (uint32_t)s * (4 * MATW * 4);
        const int ko = kt * PKC;
        cpa16 (sb +            d0, gQh + ko);       cpa16 (sb +            d1, gQh + ko + 8);
        cpa16 (sb + 1*MATW*4 + d0, gQl + ko);       cpa16 (sb + 1*MATW*4 + d1, gQl + ko + 8);
        cpa16p(sb + 2*MATW*4 + d0, gKh + ko, jok);  cpa16p(sb + 2*MATW*4 + d1, gKh + ko + 8, jok);
        cpa16p(sb + 3*MATW*4 + d0, gKl + ko, jok);  cpa16p(sb + 3*MATW*4 + d1, gKl + ko + 8, jok);
    };

    const int KT = DDIM / PKC;   // 32
    issue(0, 0); CPA_COMMIT();
    issue(1, 1); CPA_COMMIT();

    for (int kt = 0; kt < KT; kt++) {
        const int s = kt % PSTG;
        cpa_wait<1>();
        __syncthreads();
        const int nk = kt + 2;
        if (nk < KT) issue(nk, nk % PSTG);
        CPA_COMMIT();

        const uint32_t* pQh = smw + s * (4 * MATW);
        const uint32_t* pQl = pQh + MATW;
        const uint32_t* pKh = pQh + 2 * MATW;
        const uint32_t* pKl = pQh + 3 * MATW;

        #pragma unroll
        for (int s8 = 0; s8 < 2; s8++) {
            const int wlo = 4 * ((2 * s8    ) ^ fth) + tig;
            const int whi = 4 * ((2 * s8 + 1) ^ fth) + tig;
            uint32_t bh[4][2], bl[4][2];
            #pragma unroll
            for (int fn = 0; fn < 4; fn++) {
                const int n = (wn * 32 + fn * 8 + g) * 16;
                bh[fn][0] = pKh[n + wlo];   bh[fn][1] = pKh[n + whi];
                bl[fn][0] = pKl[n + wlo];   bl[fn][1] = pKl[n + whi];
            }
            #pragma unroll
            for (int fm = 0; fm < 4; fm++) {
                const int m = (wm * 64 + fm * 16 + g) * 16;
                uint32_t ah[4], al[4];
                ah[0] = pQh[m + wlo];          ah[1] = pQh[m + 128 + wlo];
                ah[2] = pQh[m + whi];          ah[3] = pQh[m + 128 + whi];
                al[0] = pQl[m + wlo];          al[1] = pQl[m + 128 + wlo];
                al[2] = pQl[m + whi];          al[3] = pQl[m + 128 + whi];
                #pragma unroll
                for (int fn = 0; fn < 4; fn++) {
                    mma_bf16(acc[fm][fn], ah, bh[fn]);
                    mma_bf16(acc[fm][fn], ah, bl[fn]);
                    mma_bf16(acc[fm][fn], al, bh[fn]);
                }
            }
        }
    }

    // band-masked store
    #pragma unroll
    for (int fm = 0; fm < 4; fm++) {
        #pragma unroll
        for (int half = 0; half < 2; half++) {
            const int i = i0 + wm * 64 + fm * 16 + g + half * 8;
            #pragma unroll
            for (int fn = 0; fn < 4; fn++) {
                const int jb = j0 + wn * 32 + fn * 8 + 2 * tig;
                #pragma unroll
                for (int c = 0; c < 2; c++) {
                    const int j = jb + c;
                    const int tt = j - i + APW;
                    if ((unsigned)j < (unsigned)NTOK && (unsigned)tt <= (unsigned)(2 * APW))
                        g_S[(size_t)i * BANDW + tt] = acc[fm][fn][half * 2 + c];
                }
            }
        }
    }
}

// =====================================================================
// Per-row band softmax -> d_att (fp32) + att hi/lo float slabs (tf32)
// slab layout: g_AH[jb][srow][jc], jb=j>>7, srow=i-128*jb+256, jc=j&127
// =====================================================================
__global__ __launch_bounds__(256) void softmax_band_kernel(float* __restrict__ d_att,
                                                           int write_att)
{
    const int i = blockIdx.x;
    const int t = threadIdx.x;
    const int t_lo = (i < APW) ? (APW - i) : 0;
    const int jmax = (i + APW < NTOK - 1) ? (i + APW) : (NTOK - 1);
    const int t_hi = jmax - i + APW;

    const float* row = g_S + (size_t)i * BANDW;
    const int t0 = t, t1 = t + 256;
    float v0 = (t0 >= t_lo && t0 <= t_hi) ? row[t0] : -INFINITY;
    float v1 = (t1 >= t_lo && t1 <= t_hi) ? row[t1] : -INFINITY;

    __shared__ float shm[8];
    __shared__ float shs[8];
    const int lane = t & 31, warp = t >> 5;

    float m = fmaxf(v0, v1);
    #pragma unroll
    for (int o = 16; o > 0; o >>= 1) m = fmaxf(m, __shfl_xor_sync(0xffffffffu, m, o));
    if (lane == 0) shm[warp] = m;
    __syncthreads();
    if (warp == 0) {
        float mm = (lane < 8) ? shm[lane] : -INFINITY;
        #pragma unroll
        for (int o = 4; o > 0; o >>= 1) mm = fmaxf(mm, __shfl_xor_sync(0xffffffffu, mm, o));
        if (lane == 0) shm[0] = mm;
    }
    __syncthreads();
    const float M = shm[0];

    const float e0 = expf(v0 - M);
    const float e1 = expf(v1 - M);
    float s = e0 + e1;
    #pragma unroll
    for (int o = 16; o > 0; o >>= 1) s += __shfl_xor_sync(0xffffffffu, s, o);
    if (lane == 0) shs[warp] = s;
    __syncthreads();
    if (warp == 0) {
        float ss = (lane < 8) ? shs[lane] : 0.f;
        #pragma unroll
        for (int o = 4; o > 0; o >>= 1) ss += __shfl_xor_sync(0xffffffffu, ss, o);
        if (lane == 0) shs[0] = ss;
    }
    __syncthreads();
    const float inv = 1.0f / shs[0];

    #pragma unroll
    for (int q = 0; q < 2; q++) {
        const int tt = q ? t1 : t0;
        const float e = q ? e1 : e0;
        if (tt >= t_lo && tt <= t_hi) {
            const float w = e * inv;
            const int j = i - APW + tt;
            const int jb = j >> 7;
            const size_t sidx = ((size_t)jb * SLABR + (i - jb * 128 + 256)) * 128 + (j & 127);
            const float h = tf32f(w);
            g_AH[sidx] = h;
            g_AL[sidx] = tf32f(w - h);
            if (write_att) d_att[(size_t)i * NTOK + j] = w;
        }
    }
}

// =====================================================================
// attv: y0 = att^T @ V, 2-term tf32 mma.sync (proven round-7 engine);
// epilogue writes y0 as bf16 hi/lo for the bf16 Wo stage.
// =====================================================================
#define AVR  136
#define AVTSS (16 * AVR)
#define ASTG 4

__global__ __launch_bounds__(256, 2) void attv3_mma()
{
    extern __shared__ float sm[];
    const int NM = 3;

    const int t = threadIdx.x;
    const int warp = t >> 5, lane = t & 31;
    const int g = lane >> 2, tig = lane & 3;
    const int wm = warp >> 2, wn = warp & 3;

    const int jb = blockIdx.y;
    const int j0 = jb * 128;
    const int d0 = blockIdx.x * 128;

    const float* slabH = g_AH + (size_t)jb * SLABR * 128;
    const float* slabL = g_AL + (size_t)jb * SLABR * 128;

    const int ft = t >> 4;
    const int fq = (t & 15) * 8;
    const uint32_t base = s2u(sm);
    const uint32_t doff = (uint32_t)(ft * AVR + fq) * 4;

    float acc[4][4][4] = {};

    auto issue = [&](int kt, int s) {
        const int srow = kt * 16 + ft;
        const int iv = j0 - 256 + srow;
        const bool ok = ((unsigned)iv < (unsigned)NTOK);
        const int ivc = ok ? iv : 0;
        const uint32_t sb = base + (uint32_t)(s * NM) * (AVTSS * 4) + doff;
        const float* pH = slabH + (size_t)srow * 128 + fq;
        const float* pL = slabL + (size_t)srow * 128 + fq;
        const float* pV = g_V + (size_t)ivc * DDIM + d0 + fq;
        cpa16 (sb, pH);                     cpa16 (sb + 16, pH + 4);
        cpa16 (sb + AVTSS * 4, pL);         cpa16 (sb + AVTSS * 4 + 16, pL + 4);
        cpa16p(sb + 2 * AVTSS * 4, pV, ok); cpa16p(sb + 2 * AVTSS * 4 + 16, pV + 4, ok);
    };

    const int KT = SLABR / 16;    // 40
    #pragma unroll
    for (int p = 0; p < ASTG - 1; p++) { issue(p, p); CPA_COMMIT(); }

    for (int kt = 0; kt < KT; kt++) {
        const int s = kt & (ASTG - 1);
        cpa_wait<ASTG - 2>();
        __syncthreads();
        const int nk = kt + ASTG - 1;
        if (nk < KT) issue(nk, nk & (ASTG - 1));
        CPA_COMMIT();

        const float* pAh = sm + (s * NM) * AVTSS;
        const float* pAl = pAh + AVTSS;
        const float* pV  = pAh + 2 * AVTSS;

        #pragma unroll
        for (int s8 = 0; s8 < 2; s8++) {
            const int kk = 8 * s8 + tig;
            const int r0 = kk * AVR;
            const int r1 = (kk + 4) * AVR;
            float ah[4][4], al[4][4], bv[4][2];
            #pragma unroll
            for (int fm = 0; fm < 4; fm++) {
                const int m = wm * 64 + fm * 16 + g;
                ah[fm][0] = pAh[r0 + m];      ah[fm][1] = pAh[r0 + m + 8];
                ah[fm][2] = pAh[r1 + m];      ah[fm][3] = pAh[r1 + m + 8];
                al[fm][0] = pAl[r0 + m];      al[fm][1] = pAl[r0 + m + 8];
                al[fm][2] = pAl[r1 + m];      al[fm][3] = pAl[r1 + m + 8];
            }
            #pragma unroll
            for (int fn = 0; fn < 4; fn++) {
                const int n = wn * 32 + fn * 8 + g;
                bv[fn][0] = pV[r0 + n];
                bv[fn][1] = pV[r1 + n];
            }
            #pragma unroll
            for (int fm = 0; fm < 4; fm++)
                #pragma unroll
                for (int fn = 0; fn < 4; fn++) {
                    mma_tf32(acc[fm][fn], ah[fm], bv[fn]);
                    mma_tf32(acc[fm][fn], al[fm], bv[fn]);
                }
        }
    }

    #pragma unroll
    for (int fm = 0; fm < 4; fm++) {
        #pragma unroll
        for (int half = 0; half < 2; half++) {
            const int j = j0 + wm * 64 + fm * 16 + g + half * 8;
            #pragma unroll
            for (int fn = 0; fn < 4; fn++) {
                const int d = d0 + wn * 32 + fn * 8 + 2 * tig;
                const size_t bidx = (size_t)j * DDIM + d;
                float v0 = acc[fm][fn][half * 2 + 0];
                float v1 = acc[fm][fn][half * 2 + 1];
                __nv_bfloat16 h0 = __float2bfloat16(v0);
                __nv_bfloat16 h1 = __float2bfloat16(v1);
                __nv_bfloat162 hv; hv.x = h0; hv.y = h1;
                __nv_bfloat162 lv;
                lv.x = __float2bfloat16(v0 - __bfloat162float(h0));
                lv.y = __float2bfloat16(v1 - __bfloat162float(h1));
                *(__nv_bfloat162*)(g_y0hb + bidx) = hv;
                *(__nv_bfloat162*)(g_y0lb + bidx) = lv;
            }
        }
    }
}

// =====================================================================
extern "C" void kernel_launch(void* const* d_in, const int* in_sizes, int n_in,
                              void* d_out, int out_size)
{
    const float* x  = (const float*)d_in[0];
    const float* Wq = (const float*)d_in[1];
    const float* Wk = (const float*)d_in[2];
    const float* Wv = (const float*)d_in[3];
    const float* Wo = (const float*)d_in[4];

    __nv_bfloat16 *xhb, *xlb, *wbf, *qhb, *qlb, *khb, *klb, *y0hb, *y0lb;
    float *vp;
    cudaGetSymbolAddress((void**)&xhb,  g_xhb);
    cudaGetSymbolAddress((void**)&xlb,  g_xlb);
    cudaGetSymbolAddress((void**)&wbf,  g_Wbf);
    cudaGetSymbolAddress((void**)&qhb,  g_Qhb);
    cudaGetSymbolAddress((void**)&qlb,  g_Qlb);
    cudaGetSymbolAddress((void**)&khb,  g_Khb);
    cudaGetSymbolAddress((void**)&klb,  g_Klb);
    cudaGetSymbolAddress((void**)&y0hb, g_y0hb);
    cudaGetSymbolAddress((void**)&y0lb, g_y0lb);
    cudaGetSymbolAddress((void**)&vp,   g_V);

    const size_t n2 = (size_t)DDIM * DDIM;
    __nv_bfloat16* wqh = wbf;            __nv_bfloat16* wql = wbf + n2;
    __nv_bfloat16* wkh = wbf + 2 * n2;   __nv_bfloat16* wkl = wbf + 3 * n2;
    __nv_bfloat16* wvh = wbf + 4 * n2;   __nv_bfloat16* wvl = wbf + 5 * n2;
    __nv_bfloat16* woh = wbf + 6 * n2;   __nv_bfloat16* wol = wbf + 7 * n2;

    const size_t yel = (size_t)NTOK * DDIM;
    const size_t ael = (size_t)NTOK * NTOK;
    float* d_y;
    float* d_att;
    int write_att;
    if ((size_t)out_size >= yel + ael) {
        d_y = (float*)d_out;
        d_att = (float*)d_out + yel;
        write_att = 1;
    } else if ((size_t)out_size >= ael) {
        d_y = vp;                        // discard y into float scratch (V no longer needed)
        d_att = (float*)d_out;
        write_att = 1;
    } else {
        d_y = (float*)d_out;
        d_att = nullptr;
        write_att = 0;
    }

    // smem opt-in (idempotent, capture-safe)
    const int smemAV = ASTG * 3 * AVTSS * 4;   // ~102 KB
    cudaFuncSetAttribute(pg_bf16<0>, cudaFuncAttributeMaxDynamicSharedMemorySize, PG_SMEM);
    cudaFuncSetAttribute(pg_bf16<1>, cudaFuncAttributeMaxDynamicSharedMemorySize, PG_SMEM);
    cudaFuncSetAttribute(pg_bf16<2>, cudaFuncAttributeMaxDynamicSharedMemorySize, PG_SMEM);
    cudaFuncSetAttribute(qk_bf16,    cudaFuncAttributeMaxDynamicSharedMemorySize, PG_SMEM);
    cudaFuncSetAttribute(attv3_mma,  cudaFuncAttributeMaxDynamicSharedMemorySize, smemAV);

    const int n1i = NTOK * DDIM;
    const int n2i = DDIM * DDIM;
    split_bf16_k<<<n1i / 256, 256>>>(x, xhb, xlb, n1i);
    split_bf16_k<<<n2i / 256, 256>>>(Wq, wqh, wql, n2i);
    split_bf16_k<<<n2i / 256, 256>>>(Wk, wkh, wkl, n2i);
    split_bf16_k<<<n2i / 256, 256>>>(Wv, wvh, wvl, n2i);
    split_bf16_k<<<n2i / 256, 256>>>(Wo, woh, wol, n2i);

    const dim3 gP(DDIM / 128, NTOK / 128);     // (8, 64)

    // Projections, 3-term bf16
    pg_bf16<2><<<gP, 256, PG_SMEM>>>(xhb, xlb, wqh, wql, nullptr, qhb, qlb, 0.06f);
    pg_bf16<2><<<gP, 256, PG_SMEM>>>(xhb, xlb, wkh, wkl, nullptr, khb, klb, 1.0f);
    pg_bf16<1><<<gP, 256, PG_SMEM>>>(xhb, xlb, wvh, wvl, vp, nullptr, nullptr, 1.0f);

    // banded logits, 3-term bf16 on split Q/K
    qk_bf16<<<dim3(5, NTOK / 128), 256, PG_SMEM>>>();

    if (write_att)
        cudaMemsetAsync(d_att, 0, ael * sizeof(float));
    softmax_band_kernel<<<NTOK, 256>>>(d_att, write_att);

    // y0 = att^T @ V (2-term tf32), bf16-split output
    attv3_mma<<<dim3(DDIM / 128, NTOK / 128), 256, smemAV>>>();

    // y = y0 @ Wo^T, 3-term bf16
    pg_bf16<0><<<gP, 256, PG_SMEM>>>(y0hb, y0lb, woh, wol, d_y, nullptr, nullptr, 1.0f);
}

// round 10
// speedup vs baseline: 1.9118x; 1.0305x over previous
#include <cuda_runtime.h>
#include <cuda_bf16.h>
#include <math.h>
#include <stdint.h>

#define NTOK 8192
#define DDIM 1024
#define APW  249            // band: |i-j| <= 249
#define BANDW 512           // raw logits band stride
#define NSLAB (NTOK / 128)  // 64 j-blocks
#define SLABK 320           // i-pairs per slab: 640 i rows / 2
#define SLABW (SLABK * 128) // u32 words per slab

// ---------------- scratch (static device arrays; zero-initialized) ----------------
__device__ __nv_bfloat16 g_xhb[(size_t)NTOK * DDIM];
__device__ __nv_bfloat16 g_xlb[(size_t)NTOK * DDIM];
__device__ __nv_bfloat16 g_Wbf[(size_t)8 * DDIM * DDIM];   // per w: hi at 2w*n2, lo at (2w+1)*n2 (q,k,v,o)
__device__ __nv_bfloat16 g_Qhb[(size_t)NTOK * DDIM];
__device__ __nv_bfloat16 g_Qlb[(size_t)NTOK * DDIM];
__device__ __nv_bfloat16 g_Khb[(size_t)NTOK * DDIM];
__device__ __nv_bfloat16 g_Klb[(size_t)NTOK * DDIM];
__device__ __nv_bfloat16 g_Vthb[(size_t)DDIM * NTOK];      // V^T hi  [d][i]
__device__ __nv_bfloat16 g_Vtlb[(size_t)DDIM * NTOK];      // V^T lo
__device__ float    g_S  [(size_t)NTOK * BANDW];           // raw logits band
__device__ uint32_t g_AHb[(size_t)NSLAB * SLABW];          // att hi slabs, u32 = (i even, i odd) bf16 pair
__device__ uint32_t g_ALb[(size_t)NSLAB * SLABW];          // att lo slabs
__device__ __nv_bfloat16 g_y0hb[(size_t)NTOK * DDIM];      // y0 bf16 hi
__device__ __nv_bfloat16 g_y0lb[(size_t)NTOK * DDIM];      // y0 bf16 lo
__device__ float g_scr[(size_t)NTOK * DDIM];               // defensive y sink

// ---------------- helpers ----------------
__device__ __forceinline__ void mma_bf16(float c[4], const uint32_t a[4], const uint32_t b[2]) {
    asm volatile(
        "mma.sync.aligned.m16n8k16.row.col.f32.bf16.bf16.f32 "
        "{%0,%1,%2,%3}, {%4,%5,%6,%7}, {%8,%9}, {%0,%1,%2,%3};"
        : "+f"(c[0]), "+f"(c[1]), "+f"(c[2]), "+f"(c[3])
        : "r"(a[0]), "r"(a[1]), "r"(a[2]), "r"(a[3]), "r"(b[0]), "r"(b[1]));
}

__device__ __forceinline__ uint32_t s2u(const void* p) {
    return (uint32_t)__cvta_generic_to_shared(p);
}
__device__ __forceinline__ void cpa16(uint32_t dst, const void* src) {
    asm volatile("cp.async.cg.shared.global [%0], [%1], 16;" :: "r"(dst), "l"(src));
}
__device__ __forceinline__ void cpa16p(uint32_t dst, const void* src, bool ok) {
    int sz = ok ? 16 : 0;
    asm volatile("cp.async.cg.shared.global [%0], [%1], 16, %2;" :: "r"(dst), "l"(src), "r"(sz));
}
#define CPA_COMMIT() asm volatile("cp.async.commit_group;")
template<int N> __device__ __forceinline__ void cpa_wait() {
    asm volatile("cp.async.wait_group %0;" :: "n"(N));
}

// ---------------- prep: bf16 hi/lo splits ----------------
__global__ void split_bf16_k(const float* __restrict__ src,
                             __nv_bfloat16* __restrict__ hi,
                             __nv_bfloat16* __restrict__ lo, int n) {
    int i = blockIdx.x * blockDim.x + threadIdx.x;
    if (i < n) {
        float v = src[i];
        __nv_bfloat16 h = __float2bfloat16(v);
        hi[i] = h;
        lo[i] = __float2bfloat16(v - __bfloat162float(h));
    }
}

// fused 4-way W split into g_Wbf
__global__ void split4_k(const float* __restrict__ w0, const float* __restrict__ w1,
                         const float* __restrict__ w2, const float* __restrict__ w3) {
    const int n2 = DDIM * DDIM;
    const int w = blockIdx.x >> 12;                 // 4096 blocks per matrix
    const int i = ((blockIdx.x & 4095) << 8) + threadIdx.x;
    const float* src = (w == 0) ? w0 : (w == 1) ? w1 : (w == 2) ? w2 : w3;
    float v = src[i];
    __nv_bfloat16 h = __float2bfloat16(v);
    g_Wbf[(size_t)(2 * w) * n2 + i] = h;
    g_Wbf[(size_t)(2 * w + 1) * n2 + i] = __float2bfloat16(v - __bfloat162float(h));
}

// =====================================================================
// bf16 3-term engine: C[M,Nn] = alpha * (Ah+Al)[M,1024] @ (Bh+Bl)[Nn,1024]^T
// terms hh + hl + lh via mma.sync.m16n8k16 (fp32 accum).
// 128x128 CTA, 256 thr = 8 warps, warp tile 64x32. K fixed = 1024.
// smem rows of 32 bf16 (64B = 4 x 16B chunks), chunk swizzle c^((row>>1)&3).
// 3-stage cp.async; 4 matrices/stage = 32KB/stage.
// OUT: 0 = fp32 C, 2 = bf16 split (Cbh/Cbl)
// =====================================================================
#define PKC  32
#define MATW 2048               // u32 words per matrix-stage
#define PSTG 3
#define PG_SMEM (PSTG * 4 * MATW * 4)   // 98304 B

template<int OUT>
__global__ __launch_bounds__(256, 2) void pg_bf16(
    const __nv_bfloat16* __restrict__ Ah, const __nv_bfloat16* __restrict__ Al,
    const __nv_bfloat16* __restrict__ Bh, const __nv_bfloat16* __restrict__ Bl,
    float* __restrict__ Cf, __nv_bfloat16* __restrict__ Cbh,
    __nv_bfloat16* __restrict__ Cbl, int Nn, float alpha)
{
    extern __shared__ uint32_t smw[];

    const int t = threadIdx.x;
    const int warp = t >> 5, lane = t & 31;
    const int g = lane >> 2, tig = lane & 3;
    const int wm = warp >> 2, wn = warp & 3;
    const int fth = (g >> 1) & 3;

    const int rowA0 = blockIdx.y * 128;
    const int rowB0 = blockIdx.x * 128;

    const int fr  = t >> 1;
    const int fc  = (t & 1) * 2;
    const int fsw = (fr >> 1) & 3;
    const __nv_bfloat16* gAh = Ah + (size_t)(rowA0 + fr) * DDIM + fc * 8;
    const __nv_bfloat16* gAl = Al + (size_t)(rowA0 + fr) * DDIM + fc * 8;
    const __nv_bfloat16* gBh = Bh + (size_t)(rowB0 + fr) * DDIM + fc * 8;
    const __nv_bfloat16* gBl = Bl + (size_t)(rowB0 + fr) * DDIM + fc * 8;

    const uint32_t base = s2u(smw);
    const uint32_t d0 = (uint32_t)(fr * 64 + ((fc    ) ^ fsw) * 16);
    const uint32_t d1 = (uint32_t)(fr * 64 + ((fc + 1) ^ fsw) * 16);

    float acc[4][4][4] = {};

    auto issue = [&](int kt, int s) {
        const uint32_t sb = base + (uint32_t)s * (4 * MATW * 4);
        const int ko = kt * PKC;
        cpa16(sb +            d0, gAh + ko);  cpa16(sb +            d1, gAh + ko + 8);
        cpa16(sb + 1*MATW*4 + d0, gAl + ko);  cpa16(sb + 1*MATW*4 + d1, gAl + ko + 8);
        cpa16(sb + 2*MATW*4 + d0, gBh + ko);  cpa16(sb + 2*MATW*4 + d1, gBh + ko + 8);
        cpa16(sb + 3*MATW*4 + d0, gBl + ko);  cpa16(sb + 3*MATW*4 + d1, gBl + ko + 8);
    };

    const int KT = DDIM / PKC;   // 32
    issue(0, 0); CPA_COMMIT();
    issue(1, 1); CPA_COMMIT();

    for (int kt = 0; kt < KT; kt++) {
        const int s = kt % PSTG;
        cpa_wait<1>();
        __syncthreads();
        const int nk = kt + 2;
        if (nk < KT) issue(nk, nk % PSTG);
        CPA_COMMIT();

        const uint32_t* pAh = smw + s * (4 * MATW);
        const uint32_t* pAl = pAh + MATW;
        const uint32_t* pBh = pAh + 2 * MATW;
        const uint32_t* pBl = pAh + 3 * MATW;

        #pragma unroll
        for (int s8 = 0; s8 < 2; s8++) {
            const int wlo = 4 * ((2 * s8    ) ^ fth) + tig;
            const int whi = 4 * ((2 * s8 + 1) ^ fth) + tig;
            uint32_t bh[4][2], bl[4][2];
            #pragma unroll
            for (int fn = 0; fn < 4; fn++) {
                const int n = (wn * 32 + fn * 8 + g) * 16;
                bh[fn][0] = pBh[n + wlo];   bh[fn][1] = pBh[n + whi];
                bl[fn][0] = pBl[n + wlo];   bl[fn][1] = pBl[n + whi];
            }
            #pragma unroll
            for (int fm = 0; fm < 4; fm++) {
                const int m = (wm * 64 + fm * 16 + g) * 16;
                uint32_t ah[4], al[4];
                ah[0] = pAh[m + wlo];          ah[1] = pAh[m + 128 + wlo];
                ah[2] = pAh[m + whi];          ah[3] = pAh[m + 128 + whi];
                al[0] = pAl[m + wlo];          al[1] = pAl[m + 128 + wlo];
                al[2] = pAl[m + whi];          al[3] = pAl[m + 128 + whi];
                #pragma unroll
                for (int fn = 0; fn < 4; fn++) {
                    mma_bf16(acc[fm][fn], ah, bh[fn]);
                    mma_bf16(acc[fm][fn], ah, bl[fn]);
                    mma_bf16(acc[fm][fn], al, bh[fn]);
                }
            }
        }
    }

    #pragma unroll
    for (int fm = 0; fm < 4; fm++) {
        #pragma unroll
        for (int half = 0; half < 2; half++) {
            const int m0 = rowA0 + wm * 64 + fm * 16 + g + half * 8;
            #pragma unroll
            for (int fn = 0; fn < 4; fn++) {
                const int n0 = rowB0 + wn * 32 + fn * 8 + 2 * tig;
                const size_t idx = (size_t)m0 * Nn + n0;
                float v0 = alpha * acc[fm][fn][half * 2 + 0];
                float v1 = alpha * acc[fm][fn][half * 2 + 1];
                if (OUT == 0) {
                    *(float2*)(Cf + idx) = make_float2(v0, v1);
                } else {
                    __nv_bfloat16 h0 = __float2bfloat16(v0);
                    __nv_bfloat16 h1 = __float2bfloat16(v1);
                    __nv_bfloat162 hv; hv.x = h0; hv.y = h1;
                    __nv_bfloat162 lv;
                    lv.x = __float2bfloat16(v0 - __bfloat162float(h0));
                    lv.y = __float2bfloat16(v1 - __bfloat162float(h1));
                    *(__nv_bfloat162*)(Cbh + idx) = hv;
                    *(__nv_bfloat162*)(Cbl + idx) = lv;
                }
            }
        }
    }
}

// =====================================================================
// Banded logits: 3-term bf16 on split Q/K -> g_S (float band). (proven)
// =====================================================================
__global__ __launch_bounds__(256, 2) void qk_bf16()
{
    extern __shared__ uint32_t smw[];

    const int t = threadIdx.x;
    const int warp = t >> 5, lane = t & 31;
    const int g = lane >> 2, tig = lane & 3;
    const int wm = warp >> 2, wn = warp & 3;
    const int fth = (g >> 1) & 3;

    const int i0 = blockIdx.y * 128;
    const int j0 = i0 - APW + (int)blockIdx.x * 128;

    const int fr  = t >> 1;
    const int fc  = (t & 1) * 2;
    const int fsw = (fr >> 1) & 3;

    const int jr = j0 + fr;
    const bool jok = ((unsigned)jr < (unsigned)NTOK);
    const int jrc = jok ? jr : 0;

    const __nv_bfloat16* gQh = g_Qhb + (size_t)(i0 + fr) * DDIM + fc * 8;
    const __nv_bfloat16* gQl = g_Qlb + (size_t)(i0 + fr) * DDIM + fc * 8;
    const __nv_bfloat16* gKh = g_Khb + (size_t)jrc * DDIM + fc * 8;
    const __nv_bfloat16* gKl = g_Klb + (size_t)jrc * DDIM + fc * 8;

    const uint32_t base = s2u(smw);
    const uint32_t d0 = (uint32_t)(fr * 64 + ((fc    ) ^ fsw) * 16);
    const uint32_t d1 = (uint32_t)(fr * 64 + ((fc + 1) ^ fsw) * 16);

    float acc[4][4][4] = {};

    auto issue = [&](int kt, int s) {
        const uint32_t sb = base + (uint32_t)s * (4 * MATW * 4);
        const int ko = kt * PKC;
        cpa16 (sb +            d0, gQh + ko);       cpa16 (sb +            d1, gQh + ko + 8);
        cpa16 (sb + 1*MATW*4 + d0, gQl + ko);       cpa16 (sb + 1*MATW*4 + d1, gQl + ko + 8);
        cpa16p(sb + 2*MATW*4 + d0, gKh + ko, jok);  cpa16p(sb + 2*MATW*4 + d1, gKh + ko + 8, jok);
        cpa16p(sb + 3*MATW*4 + d0, gKl + ko, jok);  cpa16p(sb + 3*MATW*4 + d1, gKl + ko + 8, jok);
    };

    const int KT = DDIM / PKC;
    issue(0, 0); CPA_COMMIT();
    issue(1, 1); CPA_COMMIT();

    for (int kt = 0; kt < KT; kt++) {
        const int s = kt % PSTG;
        cpa_wait<1>();
        __syncthreads();
        const int nk = kt + 2;
        if (nk < KT) issue(nk, nk % PSTG);
        CPA_COMMIT();

        const uint32_t* pQh = smw + s * (4 * MATW);
        const uint32_t* pQl = pQh + MATW;
        const uint32_t* pKh = pQh + 2 * MATW;
        const uint32_t* pKl = pQh + 3 * MATW;

        #pragma unroll
        for (int s8 = 0; s8 < 2; s8++) {
            const int wlo = 4 * ((2 * s8    ) ^ fth) + tig;
            const int whi = 4 * ((2 * s8 + 1) ^ fth) + tig;
            uint32_t bh[4][2], bl[4][2];
            #pragma unroll
            for (int fn = 0; fn < 4; fn++) {
                const int n = (wn * 32 + fn * 8 + g) * 16;
                bh[fn][0] = pKh[n + wlo];   bh[fn][1] = pKh[n + whi];
                bl[fn][0] = pKl[n + wlo];   bl[fn][1] = pKl[n + whi];
            }
            #pragma unroll
            for (int fm = 0; fm < 4; fm++) {
                const int m = (wm * 64 + fm * 16 + g) * 16;
                uint32_t ah[4], al[4];
                ah[0] = pQh[m + wlo];          ah[1] = pQh[m + 128 + wlo];
                ah[2] = pQh[m + whi];          ah[3] = pQh[m + 128 + whi];
                al[0] = pQl[m + wlo];          al[1] = pQl[m + 128 + wlo];
                al[2] = pQl[m + whi];          al[3] = pQl[m + 128 + whi];
                #pragma unroll
                for (int fn = 0; fn < 4; fn++) {
                    mma_bf16(acc[fm][fn], ah, bh[fn]);
                    mma_bf16(acc[fm][fn], ah, bl[fn]);
                    mma_bf16(acc[fm][fn], al, bh[fn]);
                }
            }
        }
    }

    #pragma unroll
    for (int fm = 0; fm < 4; fm++) {
        #pragma unroll
        for (int half = 0; half < 2; half++) {
            const int i = i0 + wm * 64 + fm * 16 + g + half * 8;
            #pragma unroll
            for (int fn = 0; fn < 4; fn++) {
                const int jb = j0 + wn * 32 + fn * 8 + 2 * tig;
                #pragma unroll
                for (int c = 0; c < 2; c++) {
                    const int j = jb + c;
                    const int tt = j - i + APW;
                    if ((unsigned)j < (unsigned)NTOK && (unsigned)tt <= (unsigned)(2 * APW))
                        g_S[(size_t)i * BANDW + tt] = acc[fm][fn][half * 2 + c];
                }
            }
        }
    }
}

// =====================================================================
// Band softmax -> d_att (fp32) + packed bf16 att hi/lo slabs.
// slab u32 word [jb][kp][jl] packs (att[i=2kp'][j], att[2kp'+1][j]) where
// srow = i - jb*128 + 256, kp = srow>>1; this thread writes half (srow&1).
// =====================================================================
__global__ __launch_bounds__(256) void softmax_band_kernel(float* __restrict__ d_att,
                                                           int write_att)
{
    const int i = blockIdx.x;
    const int t = threadIdx.x;
    const int t_lo = (i < APW) ? (APW - i) : 0;
    const int jmax = (i + APW < NTOK - 1) ? (i + APW) : (NTOK - 1);
    const int t_hi = jmax - i + APW;

    const float* row = g_S + (size_t)i * BANDW;
    const int t0 = t, t1 = t + 256;
    float v0 = (t0 >= t_lo && t0 <= t_hi) ? row[t0] : -INFINITY;
    float v1 = (t1 >= t_lo && t1 <= t_hi) ? row[t1] : -INFINITY;

    __shared__ float shm[8];
    __shared__ float shs[8];
    const int lane = t & 31, warp = t >> 5;

    float m = fmaxf(v0, v1);
    #pragma unroll
    for (int o = 16; o > 0; o >>= 1) m = fmaxf(m, __shfl_xor_sync(0xffffffffu, m, o));
    if (lane == 0) shm[warp] = m;
    __syncthreads();
    if (warp == 0) {
        float mm = (lane < 8) ? shm[lane] : -INFINITY;
        #pragma unroll
        for (int o = 4; o > 0; o >>= 1) mm = fmaxf(mm, __shfl_xor_sync(0xffffffffu, mm, o));
        if (lane == 0) shm[0] = mm;
    }
    __syncthreads();
    const float M = shm[0];

    const float e0 = expf(v0 - M);
    const float e1 = expf(v1 - M);
    float s = e0 + e1;
    #pragma unroll
    for (int o = 16; o > 0; o >>= 1) s += __shfl_xor_sync(0xffffffffu, s, o);
    if (lane == 0) shs[warp] = s;
    __syncthreads();
    if (warp == 0) {
        float ss = (lane < 8) ? shs[lane] : 0.f;
        #pragma unroll
        for (int o = 4; o > 0; o >>= 1) ss += __shfl_xor_sync(0xffffffffu, ss, o);
        if (lane == 0) shs[0] = ss;
    }
    __syncthreads();
    const float inv = 1.0f / shs[0];

    #pragma unroll
    for (int q = 0; q < 2; q++) {
        const int tt = q ? t1 : t0;
        const float e = q ? e1 : e0;
        if (tt >= t_lo && tt <= t_hi) {
            const float w = e * inv;
            const int j = i - APW + tt;
            const int jb = j >> 7;
            const int srow = i - jb * 128 + 256;
            const size_t widx = ((size_t)jb * SLABK + (srow >> 1)) * 128 + (j & 127);
            const int hh = srow & 1;
            const __nv_bfloat16 h = __float2bfloat16(w);
            ((__nv_bfloat16*)g_AHb)[widx * 2 + hh] = h;
            ((__nv_bfloat16*)g_ALb)[widx * 2 + hh] =
                __float2bfloat16(w - __bfloat162float(h));
            if (write_att) d_att[(size_t)i * NTOK + j] = w;
        }
    }
}

// =====================================================================
// attv bf16: y0[j,d] = sum_i att[i,j]*V[i,d] over i-window [j0-256, j0+384)
// 3 terms: Ah*Bh + Ah*Bl + Al*Bh;  A = att^T from packed slabs (kp-major,
// stride 136 words, conflict-free), B = V^T rows (pg-style 64B-row swizzle).
// 128(j) x 128(d) CTA, 256 thr, warp tile 64x32, 3-stage cp.async.
// Epilogue: y0 as bf16 hi/lo for the Wo stage.
// =====================================================================
#define AAW 136                  // A smem row stride (words) per kp row
#define AAS (16 * AAW)           // A matrix words per stage (16 kp rows)
#define ABS 2048                 // B matrix words per stage (128 rows * 16)
#define ASTGW (2 * AAS + 2 * ABS)           // words per stage
#define AV_SMEM (PSTG * ASTGW * 4)          // bytes

__global__ __launch_bounds__(256, 2) void attv_bf16()
{
    extern __shared__ uint32_t smw[];

    const int t = threadIdx.x;
    const int warp = t >> 5, lane = t & 31;
    const int g = lane >> 2, tig = lane & 3;
    const int wm = warp >> 2, wn = warp & 3;
    const int fth = (g >> 1) & 3;

    const int jb = blockIdx.y;
    const int j0 = jb * 128;
    const int d0 = blockIdx.x * 128;

    const uint32_t* slabH = g_AHb + (size_t)jb * SLABW;
    const uint32_t* slabL = g_ALb + (size_t)jb * SLABW;

    // A fill: kp row ft = t>>4 (0..15), words fw = (t&15)*8
    const int ft = t >> 4;
    const int fw = (t & 15) * 8;
    // B fill: d row fr = t>>1, chunk pair fc = (t&1)*2
    const int fr  = t >> 1;
    const int fc  = (t & 1) * 2;
    const int fsw = (fr >> 1) & 3;

    const uint32_t base = s2u(smw);
    const uint32_t aoff = (uint32_t)(ft * AAW + fw) * 4;
    const uint32_t b0 = (uint32_t)(fr * 64 + ((fc    ) ^ fsw) * 16);
    const uint32_t b1 = (uint32_t)(fr * 64 + ((fc + 1) ^ fsw) * 16);

    const __nv_bfloat16* gVh = g_Vthb + (size_t)(d0 + fr) * NTOK;
    const __nv_bfloat16* gVl = g_Vtlb + (size_t)(d0 + fr) * NTOK;

    float acc[4][4][4] = {};

    auto issue = [&](int kt, int s) {
        const uint32_t sb = base + (uint32_t)s * (ASTGW * 4);
        // A (att slabs): kp rows kt*16+ft, words fw..fw+7 — always valid
        const uint32_t* sH = slabH + (size_t)(kt * 16 + ft) * 128 + fw;
        const uint32_t* sL = slabL + (size_t)(kt * 16 + ft) * 128 + fw;
        cpa16(sb + aoff, sH);                 cpa16(sb + aoff + 16, sH + 4);
        cpa16(sb + AAS * 4 + aoff, sL);       cpa16(sb + AAS * 4 + aoff + 16, sL + 4);
        // B (V^T): i chunk of 32 starting at j0-256+kt*32; per-16B predicate
        const int iv0 = j0 - 256 + kt * 32 + fc * 8;
        const bool ok0 = ((unsigned)iv0 < (unsigned)NTOK);
        const bool ok1 = ((unsigned)(iv0 + 8) < (unsigned)NTOK);
        const uint32_t bbase = sb + 2 * AAS * 4;
        cpa16p(bbase + b0, gVh + iv0, ok0);
        cpa16p(bbase + b1, gVh + iv0 + 8, ok1);
        cpa16p(bbase + ABS * 4 + b0, gVl + iv0, ok0);
        cpa16p(bbase + ABS * 4 + b1, gVl + iv0 + 8, ok1);
    };

    const int KT = 20;          // 640 / 32
    issue(0, 0); CPA_COMMIT();
    issue(1, 1); CPA_COMMIT();

    for (int kt = 0; kt < KT; kt++) {
        const int s = kt % PSTG;
        cpa_wait<1>();
        __syncthreads();
        const int nk = kt + 2;
        if (nk < KT) issue(nk, nk % PSTG);
        CPA_COMMIT();

        const uint32_t* pAh = smw + s * ASTGW;
        const uint32_t* pAl = pAh + AAS;
        const uint32_t* pBh = pAh + 2 * AAS;
        const uint32_t* pBl = pBh + ABS;

        #pragma unroll
        for (int s8 = 0; s8 < 2; s8++) {
            const int wlo = 4 * ((2 * s8    ) ^ fth) + tig;
            const int whi = 4 * ((2 * s8 + 1) ^ fth) + tig;
            const int r0 = (s8 * 8 + tig) * AAW;
            const int r1 = (s8 * 8 + tig + 4) * AAW;
            uint32_t bh[4][2], bl[4][2];
            #pragma unroll
            for (int fn = 0; fn < 4; fn++) {
                const int n = (wn * 32 + fn * 8 + g) * 16;
                bh[fn][0] = pBh[n + wlo];   bh[fn][1] = pBh[n + whi];
                bl[fn][0] = pBl[n + wlo];   bl[fn][1] = pBl[n + whi];
            }
            #pragma unroll
            for (int fm = 0; fm < 4; fm++) {
                const int m = wm * 64 + fm * 16 + g;
                uint32_t ah[4], al[4];
                ah[0] = pAh[r0 + m];        ah[1] = pAh[r0 + m + 8];
                ah[2] = pAh[r1 + m];        ah[3] = pAh[r1 + m + 8];
                al[0] = pAl[r0 + m];        al[1] = pAl[r0 + m + 8];
                al[2] = pAl[r1 + m];        al[3] = pAl[r1 + m + 8];
                #pragma unroll
                for (int fn = 0; fn < 4; fn++) {
                    mma_bf16(acc[fm][fn], ah, bh[fn]);
                    mma_bf16(acc[fm][fn], ah, bl[fn]);
                    mma_bf16(acc[fm][fn], al, bh[fn]);
                }
            }
        }
    }

    #pragma unroll
    for (int fm = 0; fm < 4; fm++) {
        #pragma unroll
        for (int half = 0; half < 2; half++) {
            const int j = j0 + wm * 64 + fm * 16 + g + half * 8;
            #pragma unroll
            for (int fn = 0; fn < 4; fn++) {
                const int d = d0 + wn * 32 + fn * 8 + 2 * tig;
                const size_t bidx = (size_t)j * DDIM + d;
                float v0 = acc[fm][fn][half * 2 + 0];
                float v1 = acc[fm][fn][half * 2 + 1];
                __nv_bfloat16 h0 = __float2bfloat16(v0);
                __nv_bfloat16 h1 = __float2bfloat16(v1);
                __nv_bfloat162 hv; hv.x = h0; hv.y = h1;
                __nv_bfloat162 lv;
                lv.x = __float2bfloat16(v0 - __bfloat162float(h0));
                lv.y = __float2bfloat16(v1 - __bfloat162float(h1));
                *(__nv_bfloat162*)(g_y0hb + bidx) = hv;
                *(__nv_bfloat162*)(g_y0lb + bidx) = lv;
            }
        }
    }
}

// =====================================================================
extern "C" void kernel_launch(void* const* d_in, const int* in_sizes, int n_in,
                              void* d_out, int out_size)
{
    const float* x  = (const float*)d_in[0];
    const float* Wq = (const float*)d_in[1];
    const float* Wk = (const float*)d_in[2];
    const float* Wv = (const float*)d_in[3];
    const float* Wo = (const float*)d_in[4];

    __nv_bfloat16 *xhb, *xlb, *wbf, *qhb, *qlb, *khb, *klb, *vthb, *vtlb, *y0hb, *y0lb;
    float* scr;
    cudaGetSymbolAddress((void**)&xhb,  g_xhb);
    cudaGetSymbolAddress((void**)&xlb,  g_xlb);
    cudaGetSymbolAddress((void**)&wbf,  g_Wbf);
    cudaGetSymbolAddress((void**)&qhb,  g_Qhb);
    cudaGetSymbolAddress((void**)&qlb,  g_Qlb);
    cudaGetSymbolAddress((void**)&khb,  g_Khb);
    cudaGetSymbolAddress((void**)&klb,  g_Klb);
    cudaGetSymbolAddress((void**)&vthb, g_Vthb);
    cudaGetSymbolAddress((void**)&vtlb, g_Vtlb);
    cudaGetSymbolAddress((void**)&y0hb, g_y0hb);
    cudaGetSymbolAddress((void**)&y0lb, g_y0lb);
    cudaGetSymbolAddress((void**)&scr,  g_scr);

    const size_t n2 = (size_t)DDIM * DDIM;
    __nv_bfloat16* wqh = wbf;            __nv_bfloat16* wql = wbf + n2;
    __nv_bfloat16* wkh = wbf + 2 * n2;   __nv_bfloat16* wkl = wbf + 3 * n2;
    __nv_bfloat16* wvh = wbf + 4 * n2;   __nv_bfloat16* wvl = wbf + 5 * n2;
    __nv_bfloat16* woh = wbf + 6 * n2;   __nv_bfloat16* wol = wbf + 7 * n2;

    const size_t yel = (size_t)NTOK * DDIM;
    const size_t ael = (size_t)NTOK * NTOK;
    float* d_y;
    float* d_att;
    int write_att;
    if ((size_t)out_size >= yel + ael) {
        d_y = (float*)d_out;
        d_att = (float*)d_out + yel;
        write_att = 1;
    } else if ((size_t)out_size >= ael) {
        d_y = scr;
        d_att = (float*)d_out;
        write_att = 1;
    } else {
        d_y = (float*)d_out;
        d_att = nullptr;
        write_att = 0;
    }

    // smem opt-in (idempotent, capture-safe)
    cudaFuncSetAttribute(pg_bf16<0>, cudaFuncAttributeMaxDynamicSharedMemorySize, PG_SMEM);
    cudaFuncSetAttribute(pg_bf16<2>, cudaFuncAttributeMaxDynamicSharedMemorySize, PG_SMEM);
    cudaFuncSetAttribute(qk_bf16,    cudaFuncAttributeMaxDynamicSharedMemorySize, PG_SMEM);
    cudaFuncSetAttribute(attv_bf16,  cudaFuncAttributeMaxDynamicSharedMemorySize, AV_SMEM);

    const int n1i = NTOK * DDIM;
    split_bf16_k<<<n1i / 256, 256>>>(x, xhb, xlb, n1i);
    split4_k<<<4 * 4096, 256>>>(Wq, Wk, Wv, Wo);

    const dim3 gP(DDIM / 128, NTOK / 128);     // (8, 64)  M=8192, N=1024
    const dim3 gVt(NTOK / 128, DDIM / 128);    // (64, 8)  M=1024, N=8192

    // Q, K projections (3-term), bf16-split outputs
    pg_bf16<2><<<gP, 256, PG_SMEM>>>(xhb, xlb, wqh, wql, nullptr, qhb, qlb, DDIM, 0.06f);
    pg_bf16<2><<<gP, 256, PG_SMEM>>>(xhb, xlb, wkh, wkl, nullptr, khb, klb, DDIM, 1.0f);
    // V^T = Wv @ x^T (3-term), bf16-split output [d][i]
    pg_bf16<2><<<gVt, 256, PG_SMEM>>>(wvh, wvl, xhb, xlb, nullptr, vthb, vtlb, NTOK, 1.0f);

    // banded logits (3-term bf16)
    qk_bf16<<<dim3(5, NTOK / 128), 256, PG_SMEM>>>();

    if (write_att)
        cudaMemsetAsync(d_att, 0, ael * sizeof(float));
    softmax_band_kernel<<<NTOK, 256>>>(d_att, write_att);

    // y0 = att^T @ V (3-term bf16), bf16-split output
    attv_bf16<<<dim3(DDIM / 128, NTOK / 128), 256, AV_SMEM>>>();

    // y = y0 @ Wo^T (3-term bf16)
    pg_bf16<0><<<gP, 256, PG_SMEM>>>(y0hb, y0lb, woh, wol, d_y, nullptr, nullptr, DDIM, 1.0f);
}

// round 11
// speedup vs baseline: 1.9257x; 1.0072x over previous
#include <cuda_runtime.h>
#include <cuda_bf16.h>
#include <math.h>
#include <stdint.h>

#define NTOK 8192
#define DDIM 1024
#define APW  249            // band: |i-j| <= 249
#define BANDW 512           // raw logits band stride
#define NSLAB (NTOK / 128)  // 64 j-blocks
#define SLABK 320           // i-pairs per slab: 640 i rows / 2
#define SLABW (SLABK * 128) // u32 words per slab

// ---------------- scratch (static device arrays; zero-initialized) ----------------
__device__ __nv_bfloat16 g_xhb[(size_t)NTOK * DDIM];
__device__ __nv_bfloat16 g_xlb[(size_t)NTOK * DDIM];
__device__ __nv_bfloat16 g_Wbf[(size_t)8 * DDIM * DDIM];   // per w: hi at 2w*n2, lo at (2w+1)*n2 (q,k,v,o)
__device__ __nv_bfloat16 g_Qhb[(size_t)NTOK * DDIM];
__device__ __nv_bfloat16 g_Qlb[(size_t)NTOK * DDIM];
__device__ __nv_bfloat16 g_Khb[(size_t)NTOK * DDIM];
__device__ __nv_bfloat16 g_Klb[(size_t)NTOK * DDIM];
__device__ __nv_bfloat16 g_Vthb[(size_t)DDIM * NTOK];      // V^T hi  [d][i]
__device__ __nv_bfloat16 g_Vtlb[(size_t)DDIM * NTOK];      // V^T lo
__device__ float    g_S  [(size_t)NTOK * BANDW];           // raw logits band
__device__ uint32_t g_AHb[(size_t)NSLAB * SLABW];          // att hi slabs, u32 = (i even, i odd) bf16 pair
__device__ uint32_t g_ALb[(size_t)NSLAB * SLABW];          // att lo slabs
__device__ __nv_bfloat16 g_y0hb[(size_t)NTOK * DDIM];      // y0 bf16 hi
__device__ __nv_bfloat16 g_y0lb[(size_t)NTOK * DDIM];      // y0 bf16 lo
__device__ float g_scr[(size_t)NTOK * DDIM];               // defensive y sink

// ---------------- helpers ----------------
__device__ __forceinline__ void mma_bf16(float c[4], const uint32_t a[4], const uint32_t b[2]) {
    asm volatile(
        "mma.sync.aligned.m16n8k16.row.col.f32.bf16.bf16.f32 "
        "{%0,%1,%2,%3}, {%4,%5,%6,%7}, {%8,%9}, {%0,%1,%2,%3};"
        : "+f"(c[0]), "+f"(c[1]), "+f"(c[2]), "+f"(c[3])
        : "r"(a[0]), "r"(a[1]), "r"(a[2]), "r"(a[3]), "r"(b[0]), "r"(b[1]));
}

__device__ __forceinline__ uint32_t s2u(const void* p) {
    return (uint32_t)__cvta_generic_to_shared(p);
}
__device__ __forceinline__ void cpa16(uint32_t dst, const void* src) {
    asm volatile("cp.async.cg.shared.global [%0], [%1], 16;" :: "r"(dst), "l"(src));
}
__device__ __forceinline__ void cpa16p(uint32_t dst, const void* src, bool ok) {
    int sz = ok ? 16 : 0;
    asm volatile("cp.async.cg.shared.global [%0], [%1], 16, %2;" :: "r"(dst), "l"(src), "r"(sz));
}
#define CPA_COMMIT() asm volatile("cp.async.commit_group;")
template<int N> __device__ __forceinline__ void cpa_wait() {
    asm volatile("cp.async.wait_group %0;" :: "n"(N));
}

// ---------------- prep: bf16 hi/lo splits ----------------
__global__ void split_bf16_k(const float* __restrict__ src,
                             __nv_bfloat16* __restrict__ hi,
                             __nv_bfloat16* __restrict__ lo, int n) {
    int i = blockIdx.x * blockDim.x + threadIdx.x;
    if (i < n) {
        float v = src[i];
        __nv_bfloat16 h = __float2bfloat16(v);
        hi[i] = h;
        lo[i] = __float2bfloat16(v - __bfloat162float(h));
    }
}

// fused 4-way W split into g_Wbf
__global__ void split4_k(const float* __restrict__ w0, const float* __restrict__ w1,
                         const float* __restrict__ w2, const float* __restrict__ w3) {
    const int n2 = DDIM * DDIM;
    const int w = blockIdx.x >> 12;                 // 4096 blocks per matrix
    const int i = ((blockIdx.x & 4095) << 8) + threadIdx.x;
    const float* src = (w == 0) ? w0 : (w == 1) ? w1 : (w == 2) ? w2 : w3;
    float v = src[i];
    __nv_bfloat16 h = __float2bfloat16(v);
    g_Wbf[(size_t)(2 * w) * n2 + i] = h;
    g_Wbf[(size_t)(2 * w + 1) * n2 + i] = __float2bfloat16(v - __bfloat162float(h));
}

// =====================================================================
// bf16 3-term engine: C[M,Nn] = alpha * (Ah+Al)[M,1024] @ (Bh+Bl)[Nn,1024]^T
// terms hh + hl + lh via mma.sync.m16n8k16 (fp32 accum).
// RAW-chain-free issue order: each term sweeps all 4 fn accumulators before
// the next term touches the same accumulator again (reuse distance 4 MMAs).
// 128x128 CTA, 256 thr = 8 warps, warp tile 64x32. K fixed = 1024.
// OUT: 0 = fp32 C, 2 = bf16 split (Cbh/Cbl)
// =====================================================================
#define PKC  32
#define MATW 2048               // u32 words per matrix-stage
#define PSTG 3
#define PG_SMEM (PSTG * 4 * MATW * 4)   // 98304 B

template<int OUT>
__global__ __launch_bounds__(256, 2) void pg_bf16(
    const __nv_bfloat16* __restrict__ Ah, const __nv_bfloat16* __restrict__ Al,
    const __nv_bfloat16* __restrict__ Bh, const __nv_bfloat16* __restrict__ Bl,
    float* __restrict__ Cf, __nv_bfloat16* __restrict__ Cbh,
    __nv_bfloat16* __restrict__ Cbl, int Nn, float alpha)
{
    extern __shared__ uint32_t smw[];

    const int t = threadIdx.x;
    const int warp = t >> 5, lane = t & 31;
    const int g = lane >> 2, tig = lane & 3;
    const int wm = warp >> 2, wn = warp & 3;
    const int fth = (g >> 1) & 3;

    const int rowA0 = blockIdx.y * 128;
    const int rowB0 = blockIdx.x * 128;

    const int fr  = t >> 1;
    const int fc  = (t & 1) * 2;
    const int fsw = (fr >> 1) & 3;
    const __nv_bfloat16* gAh = Ah + (size_t)(rowA0 + fr) * DDIM + fc * 8;
    const __nv_bfloat16* gAl = Al + (size_t)(rowA0 + fr) * DDIM + fc * 8;
    const __nv_bfloat16* gBh = Bh + (size_t)(rowB0 + fr) * DDIM + fc * 8;
    const __nv_bfloat16* gBl = Bl + (size_t)(rowB0 + fr) * DDIM + fc * 8;

    const uint32_t base = s2u(smw);
    const uint32_t d0 = (uint32_t)(fr * 64 + ((fc    ) ^ fsw) * 16);
    const uint32_t d1 = (uint32_t)(fr * 64 + ((fc + 1) ^ fsw) * 16);

    float acc[4][4][4] = {};

    auto issue = [&](int kt, int s) {
        const uint32_t sb = base + (uint32_t)s * (4 * MATW * 4);
        const int ko = kt * PKC;
        cpa16(sb +            d0, gAh + ko);  cpa16(sb +            d1, gAh + ko + 8);
        cpa16(sb + 1*MATW*4 + d0, gAl + ko);  cpa16(sb + 1*MATW*4 + d1, gAl + ko + 8);
        cpa16(sb + 2*MATW*4 + d0, gBh + ko);  cpa16(sb + 2*MATW*4 + d1, gBh + ko + 8);
        cpa16(sb + 3*MATW*4 + d0, gBl + ko);  cpa16(sb + 3*MATW*4 + d1, gBl + ko + 8);
    };

    const int KT = DDIM / PKC;   // 32
    issue(0, 0); CPA_COMMIT();
    issue(1, 1); CPA_COMMIT();

    for (int kt = 0; kt < KT; kt++) {
        const int s = kt % PSTG;
        cpa_wait<1>();
        __syncthreads();
        const int nk = kt + 2;
        if (nk < KT) issue(nk, nk % PSTG);
        CPA_COMMIT();

        const uint32_t* pAh = smw + s * (4 * MATW);
        const uint32_t* pAl = pAh + MATW;
        const uint32_t* pBh = pAh + 2 * MATW;
        const uint32_t* pBl = pAh + 3 * MATW;

        #pragma unroll
        for (int s8 = 0; s8 < 2; s8++) {
            const int wlo = 4 * ((2 * s8    ) ^ fth) + tig;
            const int whi = 4 * ((2 * s8 + 1) ^ fth) + tig;
            uint32_t bh[4][2], bl[4][2];
            #pragma unroll
            for (int fn = 0; fn < 4; fn++) {
                const int n = (wn * 32 + fn * 8 + g) * 16;
                bh[fn][0] = pBh[n + wlo];   bh[fn][1] = pBh[n + whi];
                bl[fn][0] = pBl[n + wlo];   bl[fn][1] = pBl[n + whi];
            }
            #pragma unroll
            for (int fm = 0; fm < 4; fm++) {
                const int m = (wm * 64 + fm * 16 + g) * 16;
                uint32_t ah[4], al[4];
                ah[0] = pAh[m + wlo];          ah[1] = pAh[m + 128 + wlo];
                ah[2] = pAh[m + whi];          ah[3] = pAh[m + 128 + whi];
                al[0] = pAl[m + wlo];          al[1] = pAl[m + 128 + wlo];
                al[2] = pAl[m + whi];          al[3] = pAl[m + 128 + whi];
                // term-major order: accumulator reuse distance = 4 MMAs (no RAW stall)
                #pragma unroll
                for (int fn = 0; fn < 4; fn++) mma_bf16(acc[fm][fn], ah, bh[fn]);
                #pragma unroll
                for (int fn = 0; fn < 4; fn++) mma_bf16(acc[fm][fn], ah, bl[fn]);
                #pragma unroll
                for (int fn = 0; fn < 4; fn++) mma_bf16(acc[fm][fn], al, bh[fn]);
            }
        }
    }

    #pragma unroll
    for (int fm = 0; fm < 4; fm++) {
        #pragma unroll
        for (int half = 0; half < 2; half++) {
            const int m0 = rowA0 + wm * 64 + fm * 16 + g + half * 8;
            #pragma unroll
            for (int fn = 0; fn < 4; fn++) {
                const int n0 = rowB0 + wn * 32 + fn * 8 + 2 * tig;
                const size_t idx = (size_t)m0 * Nn + n0;
                float v0 = alpha * acc[fm][fn][half * 2 + 0];
                float v1 = alpha * acc[fm][fn][half * 2 + 1];
                if (OUT == 0) {
                    *(float2*)(Cf + idx) = make_float2(v0, v1);
                } else {
                    __nv_bfloat16 h0 = __float2bfloat16(v0);
                    __nv_bfloat16 h1 = __float2bfloat16(v1);
                    __nv_bfloat162 hv; hv.x = h0; hv.y = h1;
                    __nv_bfloat162 lv;
                    lv.x = __float2bfloat16(v0 - __bfloat162float(h0));
                    lv.y = __float2bfloat16(v1 - __bfloat162float(h1));
                    *(__nv_bfloat162*)(Cbh + idx) = hv;
                    *(__nv_bfloat162*)(Cbl + idx) = lv;
                }
            }
        }
    }
}

// =====================================================================
// Banded logits: 3-term bf16 on split Q/K -> g_S (float band).
// =====================================================================
__global__ __launch_bounds__(256, 2) void qk_bf16()
{
    extern __shared__ uint32_t smw[];

    const int t = threadIdx.x;
    const int warp = t >> 5, lane = t & 31;
    const int g = lane >> 2, tig = lane & 3;
    const int wm = warp >> 2, wn = warp & 3;
    const int fth = (g >> 1) & 3;

    const int i0 = blockIdx.y * 128;
    const int j0 = i0 - APW + (int)blockIdx.x * 128;

    const int fr  = t >> 1;
    const int fc  = (t & 1) * 2;
    const int fsw = (fr >> 1) & 3;

    const int jr = j0 + fr;
    const bool jok = ((unsigned)jr < (unsigned)NTOK);
    const int jrc = jok ? jr : 0;

    const __nv_bfloat16* gQh = g_Qhb + (size_t)(i0 + fr) * DDIM + fc * 8;
    const __nv_bfloat16* gQl = g_Qlb + (size_t)(i0 + fr) * DDIM + fc * 8;
    const __nv_bfloat16* gKh = g_Khb + (size_t)jrc * DDIM + fc * 8;
    const __nv_bfloat16* gKl = g_Klb + (size_t)jrc * DDIM + fc * 8;

    const uint32_t base = s2u(smw);
    const uint32_t d0 = (uint32_t)(fr * 64 + ((fc    ) ^ fsw) * 16);
    const uint32_t d1 = (uint32_t)(fr * 64 + ((fc + 1) ^ fsw) * 16);

    float acc[4][4][4] = {};

    auto issue = [&](int kt, int s) {
        const uint32_t sb = base + (uint32_t)s * (4 * MATW * 4);
        const int ko = kt * PKC;
        cpa16 (sb +            d0, gQh + ko);       cpa16 (sb +            d1, gQh + ko + 8);
        cpa16 (sb + 1*MATW*4 + d0, gQl + ko);       cpa16 (sb + 1*MATW*4 + d1, gQl + ko + 8);
        cpa16p(sb + 2*MATW*4 + d0, gKh + ko, jok);  cpa16p(sb + 2*MATW*4 + d1, gKh + ko + 8, jok);
        cpa16p(sb + 3*MATW*4 + d0, gKl + ko, jok);  cpa16p(sb + 3*MATW*4 + d1, gKl + ko + 8, jok);
    };

    const int KT = DDIM / PKC;
    issue(0, 0); CPA_COMMIT();
    issue(1, 1); CPA_COMMIT();

    for (int kt = 0; kt < KT; kt++) {
        const int s = kt % PSTG;
        cpa_wait<1>();
        __syncthreads();
        const int nk = kt + 2;
        if (nk < KT) issue(nk, nk % PSTG);
        CPA_COMMIT();

        const uint32_t* pQh = smw + s * (4 * MATW);
        const uint32_t* pQl = pQh + MATW;
        const uint32_t* pKh = pQh + 2 * MATW;
        const uint32_t* pKl = pQh + 3 * MATW;

        #pragma unroll
        for (int s8 = 0; s8 < 2; s8++) {
            const int wlo = 4 * ((2 * s8    ) ^ fth) + tig;
            const int whi = 4 * ((2 * s8 + 1) ^ fth) + tig;
            uint32_t bh[4][2], bl[4][2];
            #pragma unroll
            for (int fn = 0; fn < 4; fn++) {
                const int n = (wn * 32 + fn * 8 + g) * 16;
                bh[fn][0] = pKh[n + wlo];   bh[fn][1] = pKh[n + whi];
                bl[fn][0] = pKl[n + wlo];   bl[fn][1] = pKl[n + whi];
            }
            #pragma unroll
            for (int fm = 0; fm < 4; fm++) {
                const int m = (wm * 64 + fm * 16 + g) * 16;
                uint32_t ah[4], al[4];
                ah[0] = pQh[m + wlo];          ah[1] = pQh[m + 128 + wlo];
                ah[2] = pQh[m + whi];          ah[3] = pQh[m + 128 + whi];
                al[0] = pQl[m + wlo];          al[1] = pQl[m + 128 + wlo];
                al[2] = pQl[m + whi];          al[3] = pQl[m + 128 + whi];
                #pragma unroll
                for (int fn = 0; fn < 4; fn++) mma_bf16(acc[fm][fn], ah, bh[fn]);
                #pragma unroll
                for (int fn = 0; fn < 4; fn++) mma_bf16(acc[fm][fn], ah, bl[fn]);
                #pragma unroll
                for (int fn = 0; fn < 4; fn++) mma_bf16(acc[fm][fn], al, bh[fn]);
            }
        }
    }

    #pragma unroll
    for (int fm = 0; fm < 4; fm++) {
        #pragma unroll
        for (int half = 0; half < 2; half++) {
            const int i = i0 + wm * 64 + fm * 16 + g + half * 8;
            #pragma unroll
            for (int fn = 0; fn < 4; fn++) {
                const int jb = j0 + wn * 32 + fn * 8 + 2 * tig;
                #pragma unroll
                for (int c = 0; c < 2; c++) {
                    const int j = jb + c;
                    const int tt = j - i + APW;
                    if ((unsigned)j < (unsigned)NTOK && (unsigned)tt <= (unsigned)(2 * APW))
                        g_S[(size_t)i * BANDW + tt] = acc[fm][fn][half * 2 + c];
                }
            }
        }
    }
}

// =====================================================================
// Band softmax -> d_att (fp32) + packed bf16 att hi/lo slabs.
// =====================================================================
__global__ __launch_bounds__(256) void softmax_band_kernel(float* __restrict__ d_att,
                                                           int write_att)
{
    const int i = blockIdx.x;
    const int t = threadIdx.x;
    const int t_lo = (i < APW) ? (APW - i) : 0;
    const int jmax = (i + APW < NTOK - 1) ? (i + APW) : (NTOK - 1);
    const int t_hi = jmax - i + APW;

    const float* row = g_S + (size_t)i * BANDW;
    const int t0 = t, t1 = t + 256;
    float v0 = (t0 >= t_lo && t0 <= t_hi) ? row[t0] : -INFINITY;
    float v1 = (t1 >= t_lo && t1 <= t_hi) ? row[t1] : -INFINITY;

    __shared__ float shm[8];
    __shared__ float shs[8];
    const int lane = t & 31, warp = t >> 5;

    float m = fmaxf(v0, v1);
    #pragma unroll
    for (int o = 16; o > 0; o >>= 1) m = fmaxf(m, __shfl_xor_sync(0xffffffffu, m, o));
    if (lane == 0) shm[warp] = m;
    __syncthreads();
    if (warp == 0) {
        float mm = (lane < 8) ? shm[lane] : -INFINITY;
        #pragma unroll
        for (int o = 4; o > 0; o >>= 1) mm = fmaxf(mm, __shfl_xor_sync(0xffffffffu, mm, o));
        if (lane == 0) shm[0] = mm;
    }
    __syncthreads();
    const float M = shm[0];

    const float e0 = expf(v0 - M);
    const float e1 = expf(v1 - M);
    float s = e0 + e1;
    #pragma unroll
    for (int o = 16; o > 0; o >>= 1) s += __shfl_xor_sync(0xffffffffu, s, o);
    if (lane == 0) shs[warp] = s;
    __syncthreads();
    if (warp == 0) {
        float ss = (lane < 8) ? shs[lane] : 0.f;
        #pragma unroll
        for (int o = 4; o > 0; o >>= 1) ss += __shfl_xor_sync(0xffffffffu, ss, o);
        if (lane == 0) shs[0] = ss;
    }
    __syncthreads();
    const float inv = 1.0f / shs[0];

    #pragma unroll
    for (int q = 0; q < 2; q++) {
        const int tt = q ? t1 : t0;
        const float e = q ? e1 : e0;
        if (tt >= t_lo && tt <= t_hi) {
            const float w = e * inv;
            const int j = i - APW + tt;
            const int jb = j >> 7;
            const int srow = i - jb * 128 + 256;
            const size_t widx = ((size_t)jb * SLABK + (srow >> 1)) * 128 + (j & 127);
            const int hh = srow & 1;
            const __nv_bfloat16 h = __float2bfloat16(w);
            ((__nv_bfloat16*)g_AHb)[widx * 2 + hh] = h;
            ((__nv_bfloat16*)g_ALb)[widx * 2 + hh] =
                __float2bfloat16(w - __bfloat162float(h));
            if (write_att) d_att[(size_t)i * NTOK + j] = w;
        }
    }
}

// =====================================================================
// attv bf16: y0[j,d] = sum_i att[i,j]*V[i,d] over i-window [j0-256, j0+384)
// 3 terms, term-major issue order (RAW-free).
// =====================================================================
#define AAW 136                  // A smem row stride (words) per kp row
#define AAS (16 * AAW)           // A matrix words per stage (16 kp rows)
#define ABS 2048                 // B matrix words per stage (128 rows * 16)
#define ASTGW (2 * AAS + 2 * ABS)           // words per stage
#define AV_SMEM (PSTG * ASTGW * 4)          // bytes

__global__ __launch_bounds__(256, 2) void attv_bf16()
{
    extern __shared__ uint32_t smw[];

    const int t = threadIdx.x;
    const int warp = t >> 5, lane = t & 31;
    const int g = lane >> 2, tig = lane & 3;
    const int wm = warp >> 2, wn = warp & 3;
    const int fth = (g >> 1) & 3;

    const int jb = blockIdx.y;
    const int j0 = jb * 128;
    const int d0 = blockIdx.x * 128;

    const uint32_t* slabH = g_AHb + (size_t)jb * SLABW;
    const uint32_t* slabL = g_ALb + (size_t)jb * SLABW;

    const int ft = t >> 4;
    const int fw = (t & 15) * 8;
    const int fr  = t >> 1;
    const int fc  = (t & 1) * 2;
    const int fsw = (fr >> 1) & 3;

    const uint32_t base = s2u(smw);
    const uint32_t aoff = (uint32_t)(ft * AAW + fw) * 4;
    const uint32_t b0 = (uint32_t)(fr * 64 + ((fc    ) ^ fsw) * 16);
    const uint32_t b1 = (uint32_t)(fr * 64 + ((fc + 1) ^ fsw) * 16);

    const __nv_bfloat16* gVh = g_Vthb + (size_t)(d0 + fr) * NTOK;
    const __nv_bfloat16* gVl = g_Vtlb + (size_t)(d0 + fr) * NTOK;

    float acc[4][4][4] = {};

    auto issue = [&](int kt, int s) {
        const uint32_t sb = base + (uint32_t)s * (ASTGW * 4);
        const uint32_t* sH = slabH + (size_t)(kt * 16 + ft) * 128 + fw;
        const uint32_t* sL = slabL + (size_t)(kt * 16 + ft) * 128 + fw;
        cpa16(sb + aoff, sH);                 cpa16(sb + aoff + 16, sH + 4);
        cpa16(sb + AAS * 4 + aoff, sL);       cpa16(sb + AAS * 4 + aoff + 16, sL + 4);
        const int iv0 = j0 - 256 + kt * 32 + fc * 8;
        const bool ok0 = ((unsigned)iv0 < (unsigned)NTOK);
        const bool ok1 = ((unsigned)(iv0 + 8) < (unsigned)NTOK);
        const uint32_t bbase = sb + 2 * AAS * 4;
        cpa16p(bbase + b0, gVh + iv0, ok0);
        cpa16p(bbase + b1, gVh + iv0 + 8, ok1);
        cpa16p(bbase + ABS * 4 + b0, gVl + iv0, ok0);
        cpa16p(bbase + ABS * 4 + b1, gVl + iv0 + 8, ok1);
    };

    const int KT = 20;          // 640 / 32
    issue(0, 0); CPA_COMMIT();
    issue(1, 1); CPA_COMMIT();

    for (int kt = 0; kt < KT; kt++) {
        const int s = kt % PSTG;
        cpa_wait<1>();
        __syncthreads();
        const int nk = kt + 2;
        if (nk < KT) issue(nk, nk % PSTG);
        CPA_COMMIT();

        const uint32_t* pAh = smw + s * ASTGW;
        const uint32_t* pAl = pAh + AAS;
        const uint32_t* pBh = pAh + 2 * AAS;
        const uint32_t* pBl = pBh + ABS;

        #pragma unroll
        for (int s8 = 0; s8 < 2; s8++) {
            const int wlo = 4 * ((2 * s8    ) ^ fth) + tig;
            const int whi = 4 * ((2 * s8 + 1) ^ fth) + tig;
            const int r0 = (s8 * 8 + tig) * AAW;
            const int r1 = (s8 * 8 + tig + 4) * AAW;
            uint32_t bh[4][2], bl[4][2];
            #pragma unroll
            for (int fn = 0; fn < 4; fn++) {
                const int n = (wn * 32 + fn * 8 + g) * 16;
                bh[fn][0] = pBh[n + wlo];   bh[fn][1] = pBh[n + whi];
                bl[fn][0] = pBl[n + wlo];   bl[fn][1] = pBl[n + whi];
            }
            #pragma unroll
            for (int fm = 0; fm < 4; fm++) {
                const int m = wm * 64 + fm * 16 + g;
                uint32_t ah[4], al[4];
                ah[0] = pAh[r0 + m];        ah[1] = pAh[r0 + m + 8];
                ah[2] = pAh[r1 + m];        ah[3] = pAh[r1 + m + 8];
                al[0] = pAl[r0 + m];        al[1] = pAl[r0 + m + 8];
                al[2] = pAl[r1 + m];        al[3] = pAl[r1 + m + 8];
                #pragma unroll
                for (int fn = 0; fn < 4; fn++) mma_bf16(acc[fm][fn], ah, bh[fn]);
                #pragma unroll
                for (int fn = 0; fn < 4; fn++) mma_bf16(acc[fm][fn], ah, bl[fn]);
                #pragma unroll
                for (int fn = 0; fn < 4; fn++) mma_bf16(acc[fm][fn], al, bh[fn]);
            }
        }
    }

    #pragma unroll
    for (int fm = 0; fm < 4; fm++) {
        #pragma unroll
        for (int half = 0; half < 2; half++) {
            const int j = j0 + wm * 64 + fm * 16 + g + half * 8;
            #pragma unroll
            for (int fn = 0; fn < 4; fn++) {
                const int d = d0 + wn * 32 + fn * 8 + 2 * tig;
                const size_t bidx = (size_t)j * DDIM + d;
                float v0 = acc[fm][fn][half * 2 + 0];
                float v1 = acc[fm][fn][half * 2 + 1];
                __nv_bfloat16 h0 = __float2bfloat16(v0);
                __nv_bfloat16 h1 = __float2bfloat16(v1);
                __nv_bfloat162 hv; hv.x = h0; hv.y = h1;
                __nv_bfloat162 lv;
                lv.x = __float2bfloat16(v0 - __bfloat162float(h0));
                lv.y = __float2bfloat16(v1 - __bfloat162float(h1));
                *(__nv_bfloat162*)(g_y0hb + bidx) = hv;
                *(__nv_bfloat162*)(g_y0lb + bidx) = lv;
            }
        }
    }
}

// =====================================================================
extern "C" void kernel_launch(void* const* d_in, const int* in_sizes, int n_in,
                              void* d_out, int out_size)
{
    const float* x  = (const float*)d_in[0];
    const float* Wq = (const float*)d_in[1];
    const float* Wk = (const float*)d_in[2];
    const float* Wv = (const float*)d_in[3];
    const float* Wo = (const float*)d_in[4];

    __nv_bfloat16 *xhb, *xlb, *wbf, *qhb, *qlb, *khb, *klb, *vthb, *vtlb, *y0hb, *y0lb;
    float* scr;
    cudaGetSymbolAddress((void**)&xhb,  g_xhb);
    cudaGetSymbolAddress((void**)&xlb,  g_xlb);
    cudaGetSymbolAddress((void**)&wbf,  g_Wbf);
    cudaGetSymbolAddress((void**)&qhb,  g_Qhb);
    cudaGetSymbolAddress((void**)&qlb,  g_Qlb);
    cudaGetSymbolAddress((void**)&khb,  g_Khb);
    cudaGetSymbolAddress((void**)&klb,  g_Klb);
    cudaGetSymbolAddress((void**)&vthb, g_Vthb);
    cudaGetSymbolAddress((void**)&vtlb, g_Vtlb);
    cudaGetSymbolAddress((void**)&y0hb, g_y0hb);
    cudaGetSymbolAddress((void**)&y0lb, g_y0lb);
    cudaGetSymbolAddress((void**)&scr,  g_scr);

    const size_t n2 = (size_t)DDIM * DDIM;
    __nv_bfloat16* wqh = wbf;            __nv_bfloat16* wql = wbf + n2;
    __nv_bfloat16* wkh = wbf + 2 * n2;   __nv_bfloat16* wkl = wbf + 3 * n2;
    __nv_bfloat16* wvh = wbf + 4 * n2;   __nv_bfloat16* wvl = wbf + 5 * n2;
    __nv_bfloat16* woh = wbf + 6 * n2;   __nv_bfloat16* wol = wbf + 7 * n2;

    const size_t yel = (size_t)NTOK * DDIM;
    const size_t ael = (size_t)NTOK * NTOK;
    float* d_y;
    float* d_att;
    int write_att;
    if ((size_t)out_size >= yel + ael) {
        d_y = (float*)d_out;
        d_att = (float*)d_out + yel;
        write_att = 1;
    } else if ((size_t)out_size >= ael) {
        d_y = scr;
        d_att = (float*)d_out;
        write_att = 1;
    } else {
        d_y = (float*)d_out;
        d_att = nullptr;
        write_att = 0;
    }

    // smem opt-in (idempotent, capture-safe)
    cudaFuncSetAttribute(pg_bf16<0>, cudaFuncAttributeMaxDynamicSharedMemorySize, PG_SMEM);
    cudaFuncSetAttribute(pg_bf16<2>, cudaFuncAttributeMaxDynamicSharedMemorySize, PG_SMEM);
    cudaFuncSetAttribute(qk_bf16,    cudaFuncAttributeMaxDynamicSharedMemorySize, PG_SMEM);
    cudaFuncSetAttribute(attv_bf16,  cudaFuncAttributeMaxDynamicSharedMemorySize, AV_SMEM);

    const int n1i = NTOK * DDIM;
    split_bf16_k<<<n1i / 256, 256>>>(x, xhb, xlb, n1i);
    split4_k<<<4 * 4096, 256>>>(Wq, Wk, Wv, Wo);

    const dim3 gP(DDIM / 128, NTOK / 128);     // (8, 64)  M=8192, N=1024
    const dim3 gVt(NTOK / 128, DDIM / 128);    // (64, 8)  M=1024, N=8192

    // Q, K projections (3-term), bf16-split outputs
    pg_bf16<2><<<gP, 256, PG_SMEM>>>(xhb, xlb, wqh, wql, nullptr, qhb, qlb, DDIM, 0.06f);
    pg_bf16<2><<<gP, 256, PG_SMEM>>>(xhb, xlb, wkh, wkl, nullptr, khb, klb, DDIM, 1.0f);
    // V^T = Wv @ x^T (3-term), bf16-split output [d][i]
    pg_bf16<2><<<gVt, 256, PG_SMEM>>>(wvh, wvl, xhb, xlb, nullptr, vthb, vtlb, NTOK, 1.0f);

    // banded logits (3-term bf16)
    qk_bf16<<<dim3(5, NTOK / 128), 256, PG_SMEM>>>();

    if (write_att)
        cudaMemsetAsync(d_att, 0, ael * sizeof(float));
    softmax_band_kernel<<<NTOK, 256>>>(d_att, write_att);

    // y0 = att^T @ V (3-term bf16), bf16-split output
    attv_bf16<<<dim3(DDIM / 128, NTOK / 128), 256, AV_SMEM>>>();

    // y = y0 @ Wo^T (3-term bf16)
    pg_bf16<0><<<gP, 256, PG_SMEM>>>(y0hb, y0lb, woh, wol, d_y, nullptr, nullptr, DDIM, 1.0f);
}